// round 13
// baseline (speedup 1.0000x reference)
#include <cuda_runtime.h>
#include <cuda_fp16.h>
#include <cstdint>

// Problem constants
#define BB   2
#define TT   2048
#define DD   1024
#define HH   16
#define DH   64
#define NC   32           // TT / 64 chunks
#define BH   32           // BB * HH
#define MM   4096         // BB * TT
#define EPSF 1e-6f

// GEMM tiling (round-10 proven config: BK=32, 3-stage cp.async, 2 CTAs/SM)
#define BM   128
#define BN   128
#define BK   32
#define NKB  (DD / BK)    // 32 k-stages
#define ROWB  80          // padded row stride bytes (32 fp16 + 16B pad)
#define TILEB (128 * ROWB)
#define STG   (2 * TILEB)
#define NSTG  3
#define SMEM_DYN (NSTG * STG)       // 61440 B

#define XN4 (MM * DD / 4)
#define WN4 (DD * DD / 4)
#define CN4 (XN4 + 4 * WN4)

// attention smem row stride: 72 fp16 = 144B (conflict-free LDSM)
#define SR 72

// Scratch (device globals; allocation is forbidden)
__device__ __half g_q[BH * TT * DH];        // [b,h,t,dh] fp16
__device__ __half g_k[BH * TT * DH];
__device__ __half g_v[BH * TT * DH];
__device__ __half g_kvh[BH * NC * DH * DH]; // per-chunk KV (fp16)
__device__ __half g_sh[BH * NC * DH * DH];  // exclusive-prefix S (fp16)
__device__ float  g_ks[BH * NC * DH];       // k-sum, then exclusive prefix (fp32)

// Persistent fp16 copies
__device__ __half g_xh[MM * DD];
__device__ __half g_wh[4 * DD * DD];        // Wq | Wk | Wv | Wo
__device__ __half g_ah[MM * DD];            // attention output

// ---------------------------------------------------------------------------
// helpers
// ---------------------------------------------------------------------------
__device__ __forceinline__ uint32_t smem_u32(const void* p) {
    uint32_t a;
    asm("{ .reg .u64 t; cvta.to.shared.u64 t, %1; cvt.u32.u64 %0, t; }"
        : "=r"(a) : "l"(p));
    return a;
}
__device__ __forceinline__ uint32_t packf2h(float lo, float hi) {
    __half2 h = __floats2half2_rn(lo, hi);
    return *(uint32_t*)&h;
}
__device__ __forceinline__ void mma16816(float* c, const uint32_t* a, const uint32_t* b) {
    asm volatile(
        "mma.sync.aligned.m16n8k16.row.col.f32.f16.f16.f32 "
        "{%0,%1,%2,%3}, {%4,%5,%6,%7}, {%8,%9}, {%0,%1,%2,%3};"
        : "+f"(c[0]), "+f"(c[1]), "+f"(c[2]), "+f"(c[3])
        : "r"(a[0]), "r"(a[1]), "r"(a[2]), "r"(a[3]), "r"(b[0]), "r"(b[1]));
}
__device__ __forceinline__ void ldsm4(uint32_t* r, uint32_t addr) {
    asm volatile("ldmatrix.sync.aligned.m8n8.x4.shared.b16 {%0,%1,%2,%3}, [%4];"
                 : "=r"(r[0]), "=r"(r[1]), "=r"(r[2]), "=r"(r[3]) : "r"(addr));
}
__device__ __forceinline__ void ldsm4t(uint32_t* r, uint32_t addr) {
    asm volatile("ldmatrix.sync.aligned.m8n8.x4.trans.shared.b16 {%0,%1,%2,%3}, [%4];"
                 : "=r"(r[0]), "=r"(r[1]), "=r"(r[2]), "=r"(r[3]) : "r"(addr));
}
__device__ __forceinline__ void cp16(uint32_t dst, const void* src) {
    asm volatile("cp.async.cg.shared.global [%0], [%1], 16;"
                 :: "r"(dst), "l"(src) : "memory");
}
#define CP_COMMIT() asm volatile("cp.async.commit_group;" ::: "memory")
#define CP_WAIT1()  asm volatile("cp.async.wait_group 1;"  ::: "memory")

// ---------------------------------------------------------------------------
// Fused one-time fp32 -> fp16 cast: x then Wq/Wk/Wv/Wo. Grid-stride, 4/thread.
// ---------------------------------------------------------------------------
__global__ __launch_bounds__(256) void conv_all(
    const float* __restrict__ x,
    const float* __restrict__ Wq, const float* __restrict__ Wk,
    const float* __restrict__ Wv, const float* __restrict__ Wo)
{
    const int stride = gridDim.x * 256;
    for (int i = blockIdx.x * 256 + threadIdx.x; i < CN4; i += stride) {
        const float* src;
        __half* dst;
        int j;
        if (i < XN4) {
            src = x; dst = g_xh; j = i;
        } else {
            const int t = i - XN4;
            const int w = t / WN4;
            j = t - w * WN4;
            src = (w == 0) ? Wq : (w == 1) ? Wk : (w == 2) ? Wv : Wo;
            dst = g_wh + (size_t)w * DD * DD;
        }
        float4 v = ((const float4*)src)[j];
        uint2 u;
        u.x = packf2h(v.x, v.y);
        u.y = packf2h(v.z, v.w);
        ((uint2*)dst)[j] = u;
    }
}

// ---------------------------------------------------------------------------
// fp16 tensor-core GEMM. head_layout: write fp16 to h0/h1/h2 in [b,h,t,dh];
// else write fp32 to o0 in [m][n]. BK=32, 2 CTAs/SM, cp.async 3-stage, ldmatrix.
// ---------------------------------------------------------------------------
__global__ __launch_bounds__(256, 2) void mma_gemm4(
    const __half* __restrict__ A, const __half* __restrict__ W,
    const float* __restrict__ bz0, const float* __restrict__ bz1, const float* __restrict__ bz2,
    float* __restrict__ o0,
    __half* __restrict__ h0, __half* __restrict__ h1, __half* __restrict__ h2,
    int f0, int f1, int f2, int head_layout)
{
    extern __shared__ char dsm[];

    const int z = blockIdx.z;
    const __half* B = W + (size_t)z * DD * DD;
    const float* bias = (z == 0) ? bz0 : (z == 1) ? bz1 : bz2;
    __half*      houtp = (z == 0) ? h0 : (z == 1) ? h1 : h2;
    const int    fm   = (z == 0) ? f0  : (z == 1) ? f1  : f2;

    const int tid  = threadIdx.x;
    const int wid  = tid >> 5, lane = tid & 31;
    const int m0   = blockIdx.y * BM, n0 = blockIdx.x * BN;
    const int wm   = (wid >> 2) * 64, wn = (wid & 3) * 32;
    const int g    = lane >> 2, tig = lane & 3;
    const uint32_t sb = smem_u32(dsm);

    float acc[4][4][4];
    #pragma unroll
    for (int i = 0; i < 4; i++)
        #pragma unroll
        for (int j = 0; j < 4; j++)
            #pragma unroll
            for (int q = 0; q < 4; q++) acc[i][j][q] = 0.f;

    const int srow = tid >> 1;
    const int scol = (tid & 1) * 16;
    const uint32_t doff = (uint32_t)srow * ROWB + scol * 2;

    auto issue = [&](int c, int s) {
        const uint32_t base = sb + s * STG;
        const int kb = c * BK;
        const __half* ap = A + (size_t)(m0 + srow) * DD + kb + scol;
        const __half* bp = B + (size_t)(n0 + srow) * DD + kb + scol;
        cp16(base + doff,              ap);
        cp16(base + doff + 16,         ap + 8);
        cp16(base + TILEB + doff,      bp);
        cp16(base + TILEB + doff + 16, bp + 8);
    };

    auto compute = [&](int s) {
        const uint32_t base = sb + s * STG;
        #pragma unroll
        for (int kt = 0; kt < 2; kt++) {
            const uint32_t kby = kt * 32;
            uint32_t bf[4][2];
            #pragma unroll
            for (int ntp = 0; ntp < 2; ntp++) {
                const uint32_t baddr = base + TILEB +
                    (uint32_t)(wn + ntp * 16 + ((lane >> 4) & 1) * 8 + (lane & 7)) * ROWB +
                    kby + ((lane >> 3) & 1) * 16;
                uint32_t t[4];
                ldsm4(t, baddr);
                bf[2 * ntp][0] = t[0];     bf[2 * ntp][1] = t[1];
                bf[2 * ntp + 1][0] = t[2]; bf[2 * ntp + 1][1] = t[3];
            }
            #pragma unroll
            for (int mt = 0; mt < 4; mt++) {
                const uint32_t aaddr = base +
                    (uint32_t)(wm + mt * 16 + ((lane >> 3) & 1) * 8 + (lane & 7)) * ROWB +
                    kby + ((lane >> 4) & 1) * 16;
                uint32_t af[4];
                ldsm4(af, aaddr);
                #pragma unroll
                for (int nt = 0; nt < 4; nt++)
                    mma16816(acc[mt][nt], af, bf[nt]);
            }
        }
    };

    issue(0, 0); CP_COMMIT();
    issue(1, 1); CP_COMMIT();

    for (int c = 0; c < NKB; c++) {
        CP_WAIT1();
        __syncthreads();
        compute(c % NSTG);
        if (c + 2 < NKB) issue(c + 2, (c + 2) % NSTG);
        CP_COMMIT();
    }

    const int hcol = (n0 + wn) >> 6;
    #pragma unroll
    for (int mt = 0; mt < 4; mt++) {
        const int r0 = m0 + wm + mt * 16 + g;
        #pragma unroll
        for (int nt = 0; nt < 4; nt++) {
            const int cn = n0 + wn + nt * 8 + 2 * tig;
            float v0 = acc[mt][nt][0] + bias[cn];
            float v1 = acc[mt][nt][1] + bias[cn + 1];
            float v2 = acc[mt][nt][2] + bias[cn];
            float v3 = acc[mt][nt][3] + bias[cn + 1];
            if (fm) {
                v0 = (v0 > 0.f) ? (v0 + 1.f) : expf(v0);
                v1 = (v1 > 0.f) ? (v1 + 1.f) : expf(v1);
                v2 = (v2 > 0.f) ? (v2 + 1.f) : expf(v2);
                v3 = (v3 > 0.f) ? (v3 + 1.f) : expf(v3);
            }
            if (head_layout) {
                const int b = r0 >> 11, t = r0 & (TT - 1);
                const int dh = cn & 63;
                __half* p = houtp + ((size_t)((b * HH + hcol) * TT + t)) * DH + dh;
                *(uint32_t*)p            = packf2h(v0, v1);
                *(uint32_t*)(p + 8 * DH) = packf2h(v2, v3);
            } else {
                float* p = o0 + (size_t)r0 * DD + cn;
                *(float2*)p            = make_float2(v0, v1);
                *(float2*)(p + 8 * DD) = make_float2(v2, v3);
            }
        }
    }
}

// ---------------------------------------------------------------------------
// chunk_kv via mma: KV[d][e] = sum_t K[t][d] V[t][e]  -> fp16 out
// ---------------------------------------------------------------------------
__global__ __launch_bounds__(128) void chunk_kv_mma()
{
    __shared__ __half Ks[64 * SR];
    __shared__ __half Vs[64 * SR];

    const int c = blockIdx.x, bh = blockIdx.y;
    const int tid = threadIdx.x;
    const int wid = tid >> 5, lane = tid & 31;
    const int g = lane >> 2, tig = lane & 3;
    const int wm = wid * 16;

    const __half* kp = g_k + ((size_t)bh * TT + c * 64) * DH;
    const __half* vp = g_v + ((size_t)bh * TT + c * 64) * DH;
    const int lr = tid >> 1, lc = (tid & 1) * 32;
    #pragma unroll
    for (int u = 0; u < 4; u++) {
        *(uint4*)(Ks + lr * SR + lc + u * 8) = *(const uint4*)(kp + lr * 64 + lc + u * 8);
        *(uint4*)(Vs + lr * SR + lc + u * 8) = *(const uint4*)(vp + lr * 64 + lc + u * 8);
    }
    __syncthreads();

    const uint32_t kb = smem_u32(Ks), vb = smem_u32(Vs);
    float acc[8][4];
    #pragma unroll
    for (int i = 0; i < 8; i++)
        #pragma unroll
        for (int q = 0; q < 4; q++) acc[i][q] = 0.f;

    #pragma unroll
    for (int ks = 0; ks < 4; ks++) {
        const int t0 = ks * 16;
        uint32_t ka[4];
        ldsm4t(ka, kb + (uint32_t)(t0 + ((lane >> 4) & 1) * 8 + (lane & 7)) * (SR * 2)
                     + wm * 2 + ((lane >> 3) & 1) * 16);
        #pragma unroll
        for (int ntp = 0; ntp < 4; ntp++) {
            uint32_t t[4];
            ldsm4t(t, vb + (uint32_t)(t0 + ((lane >> 3) & 1) * 8 + (lane & 7)) * (SR * 2)
                        + ntp * 32 + ((lane >> 4) & 1) * 16);
            uint32_t b0[2] = { t[0], t[1] }, b1[2] = { t[2], t[3] };
            mma16816(acc[2 * ntp],     ka, b0);
            mma16816(acc[2 * ntp + 1], ka, b1);
        }
    }

    __half* kvout = g_kvh + ((size_t)bh * NC + c) * 4096;
    #pragma unroll
    for (int nt = 0; nt < 8; nt++) {
        const int col = nt * 8 + 2 * tig;
        *(uint32_t*)(kvout + (wm + g) * 64 + col)     = packf2h(acc[nt][0], acc[nt][1]);
        *(uint32_t*)(kvout + (wm + g + 8) * 64 + col) = packf2h(acc[nt][2], acc[nt][3]);
    }

    if (tid < 64) {
        float s = 0.f;
        #pragma unroll 8
        for (int t = 0; t < 64; t++) s += __half2float(Ks[t * SR + tid]);
        g_ks[((size_t)bh * NC + c) * 64 + tid] = s;
    }
}

// ---------------------------------------------------------------------------
// Exclusive prefix scan across chunks; fp16 in (g_kvh), fp16 out (g_sh).
// 4 pair-positions per thread (8 halves); register-prefetched (MLP up to 128).
// grid (2, BH) x 256 threads.
// ---------------------------------------------------------------------------
__global__ __launch_bounds__(256) void prefix_scan()
{
    const int bh = blockIdx.y;
    const int t0 = blockIdx.x * 256 + threadIdx.x;   // 0..511
    const __half* basep = g_kvh + (size_t)bh * NC * 4096;
    __half* outbp = g_sh + (size_t)bh * NC * 4096;

    #pragma unroll
    for (int u = 0; u < 4; u++) {
        const int p2 = t0 + u * 512;                 // pair index 0..2047
        const __half* base = basep + p2 * 2;
        __half* outp = outbp + p2 * 2;
        __half2 v[NC];
        #pragma unroll
        for (int c = 0; c < NC; c++) v[c] = *(const __half2*)(base + c * 4096);
        float2 run = make_float2(0.f, 0.f);
        #pragma unroll
        for (int c = 0; c < NC; c++) {
            *(__half2*)(outp + c * 4096) = __floats2half2_rn(run.x, run.y);
            float2 f = __half22float2(v[c]);
            run.x += f.x; run.y += f.y;
        }
    }

    if (blockIdx.x == 0 && threadIdx.x < 64) {
        float w[NC];
        float* kbp = g_ks + (size_t)bh * NC * 64 + threadIdx.x;
        #pragma unroll
        for (int c = 0; c < NC; c++) w[c] = kbp[c * 64];
        float r2 = 0.f;
        #pragma unroll
        for (int c = 0; c < NC; c++) {
            kbp[c * 64] = r2;
            r2 += w[c];
        }
    }
}

// ---------------------------------------------------------------------------
// Attention chunk via mma: A = mask(QK^T); out = (A V + Q S) / (rowsum(A)+Qz)
// Writes fp16 g_ah for the O-gemm.
// ---------------------------------------------------------------------------
__global__ __launch_bounds__(128) void attn_mma()
{
    __shared__ __half Qs[64 * SR];
    __shared__ __half Ks[64 * SR];   // K, then reused as A
    __shared__ __half Vs[64 * SR];
    __shared__ __half Ss[64 * SR];
    __shared__ float  zs[64];

    const int c = blockIdx.x, bh = blockIdx.y;
    const int tid = threadIdx.x;
    const int wid = tid >> 5, lane = tid & 31;
    const int g = lane >> 2, tig = lane & 3;
    const int wm = wid * 16;

    const __half* qp = g_q + ((size_t)bh * TT + c * 64) * DH;
    const __half* kp = g_k + ((size_t)bh * TT + c * 64) * DH;
    const __half* vp = g_v + ((size_t)bh * TT + c * 64) * DH;
    const __half* sp = g_sh + ((size_t)bh * NC + c) * 4096;

    const int lr = tid >> 1, lc = (tid & 1) * 32;
    #pragma unroll
    for (int u = 0; u < 4; u++) {
        *(uint4*)(Qs + lr * SR + lc + u * 8) = *(const uint4*)(qp + lr * 64 + lc + u * 8);
        *(uint4*)(Ks + lr * SR + lc + u * 8) = *(const uint4*)(kp + lr * 64 + lc + u * 8);
        *(uint4*)(Vs + lr * SR + lc + u * 8) = *(const uint4*)(vp + lr * 64 + lc + u * 8);
        *(uint4*)(Ss + lr * SR + lc + u * 8) = *(const uint4*)(sp + lr * 64 + lc + u * 8);
    }
    if (tid < 64) zs[tid] = g_ks[((size_t)bh * NC + c) * 64 + tid];
    __syncthreads();

    const uint32_t qb = smem_u32(Qs), kb = smem_u32(Ks);
    const uint32_t vb = smem_u32(Vs), sb = smem_u32(Ss);

    // ---- GEMM1: A = Q K^T ----
    float aa[8][4];
    #pragma unroll
    for (int i = 0; i < 8; i++)
        #pragma unroll
        for (int q = 0; q < 4; q++) aa[i][q] = 0.f;

    #pragma unroll
    for (int ks = 0; ks < 4; ks++) {
        const uint32_t kby = ks * 32;
        uint32_t qa[4];
        ldsm4(qa, qb + (uint32_t)(wm + ((lane >> 3) & 1) * 8 + (lane & 7)) * (SR * 2)
                    + kby + ((lane >> 4) & 1) * 16);
        #pragma unroll
        for (int ntp = 0; ntp < 4; ntp++) {
            uint32_t t[4];
            ldsm4(t, kb + (uint32_t)(ntp * 16 + ((lane >> 4) & 1) * 8 + (lane & 7)) * (SR * 2)
                       + kby + ((lane >> 3) & 1) * 16);
            uint32_t b0[2] = { t[0], t[1] }, b1[2] = { t[2], t[3] };
            mma16816(aa[2 * ntp],     qa, b0);
            mma16816(aa[2 * ntp + 1], qa, b1);
        }
    }

    // mask + rowsum
    const int r0 = wm + g, r1 = r0 + 8;
    float rs0 = 0.f, rs1 = 0.f;
    #pragma unroll
    for (int nt = 0; nt < 8; nt++) {
        const int c0 = nt * 8 + 2 * tig, c1 = c0 + 1;
        if (c0 > r0) aa[nt][0] = 0.f;
        if (c1 > r0) aa[nt][1] = 0.f;
        if (c0 > r1) aa[nt][2] = 0.f;
        if (c1 > r1) aa[nt][3] = 0.f;
        rs0 += aa[nt][0] + aa[nt][1];
        rs1 += aa[nt][2] + aa[nt][3];
    }
    #pragma unroll
    for (int off = 1; off < 4; off <<= 1) {
        rs0 += __shfl_xor_sync(0xffffffffu, rs0, off);
        rs1 += __shfl_xor_sync(0xffffffffu, rs1, off);
    }

    // qz
    float qz0 = 0.f, qz1 = 0.f;
    #pragma unroll 8
    for (int d2 = 0; d2 < 32; d2++) {
        float2 z2 = *(const float2*)(zs + 2 * d2);
        float2 q0 = __half22float2(*(const __half2*)(Qs + r0 * SR + 2 * d2));
        float2 q1 = __half22float2(*(const __half2*)(Qs + r1 * SR + 2 * d2));
        qz0 += q0.x * z2.x + q0.y * z2.y;
        qz1 += q1.x * z2.x + q1.y * z2.y;
    }

    // write masked A (fp16) into Ks
    __syncthreads();
    #pragma unroll
    for (int nt = 0; nt < 8; nt++) {
        const int col = nt * 8 + 2 * tig;
        *(uint32_t*)(Ks + r0 * SR + col) = packf2h(aa[nt][0], aa[nt][1]);
        *(uint32_t*)(Ks + r1 * SR + col) = packf2h(aa[nt][2], aa[nt][3]);
    }
    __syncthreads();

    // ---- GEMM2: out = A V + GEMM3: out += Q S ----
    float oc[8][4];
    #pragma unroll
    for (int i = 0; i < 8; i++)
        #pragma unroll
        for (int q = 0; q < 4; q++) oc[i][q] = 0.f;

    #pragma unroll
    for (int ks = 0; ks < 4; ks++) {
        const uint32_t kby = ks * 32;
        uint32_t af[4];
        ldsm4(af, kb + (uint32_t)(wm + ((lane >> 3) & 1) * 8 + (lane & 7)) * (SR * 2)
                    + kby + ((lane >> 4) & 1) * 16);
        #pragma unroll
        for (int ntp = 0; ntp < 4; ntp++) {
            uint32_t t[4];
            ldsm4t(t, vb + (uint32_t)(ks * 16 + ((lane >> 3) & 1) * 8 + (lane & 7)) * (SR * 2)
                        + ntp * 32 + ((lane >> 4) & 1) * 16);
            uint32_t b0[2] = { t[0], t[1] }, b1[2] = { t[2], t[3] };
            mma16816(oc[2 * ntp],     af, b0);
            mma16816(oc[2 * ntp + 1], af, b1);
        }
    }
    #pragma unroll
    for (int ks = 0; ks < 4; ks++) {
        const uint32_t kby = ks * 32;
        uint32_t qa[4];
        ldsm4(qa, qb + (uint32_t)(wm + ((lane >> 3) & 1) * 8 + (lane & 7)) * (SR * 2)
                    + kby + ((lane >> 4) & 1) * 16);
        #pragma unroll
        for (int ntp = 0; ntp < 4; ntp++) {
            uint32_t t[4];
            ldsm4t(t, sb + (uint32_t)(ks * 16 + ((lane >> 3) & 1) * 8 + (lane & 7)) * (SR * 2)
                        + ntp * 32 + ((lane >> 4) & 1) * 16);
            uint32_t b0[2] = { t[0], t[1] }, b1[2] = { t[2], t[3] };
            mma16816(oc[2 * ntp],     qa, b0);
            mma16816(oc[2 * ntp + 1], qa, b1);
        }
    }

    const float inv0 = 1.f / fmaxf(rs0 + qz0, EPSF);
    const float inv1 = 1.f / fmaxf(rs1 + qz1, EPSF);
    const int b = bh >> 4, h = bh & 15;
    __half* p0 = g_ah + ((size_t)(b * TT + c * 64 + r0)) * DD + h * 64;
    __half* p1 = g_ah + ((size_t)(b * TT + c * 64 + r1)) * DD + h * 64;
    #pragma unroll
    for (int nt = 0; nt < 8; nt++) {
        const int col = nt * 8 + 2 * tig;
        *(uint32_t*)(p0 + col) = packf2h(oc[nt][0] * inv0, oc[nt][1] * inv0);
        *(uint32_t*)(p1 + col) = packf2h(oc[nt][2] * inv1, oc[nt][3] * inv1);
    }
}

// ---------------------------------------------------------------------------
extern "C" void kernel_launch(void* const* d_in, const int* in_sizes, int n_in,
                              void* d_out, int out_size)
{
    const float* x  = (const float*)d_in[0];
    const float* Wq = (const float*)d_in[1];
    const float* bq = (const float*)d_in[2];
    const float* Wk = (const float*)d_in[3];
    const float* bk = (const float*)d_in[4];
    const float* Wv = (const float*)d_in[5];
    const float* bv = (const float*)d_in[6];
    const float* Wo = (const float*)d_in[7];
    const float* bo = (const float*)d_in[8];
    float* out = (float*)d_out;

    __half *q, *k, *v, *xh, *wh, *ah;
    cudaGetSymbolAddress((void**)&q,  g_q);
    cudaGetSymbolAddress((void**)&k,  g_k);
    cudaGetSymbolAddress((void**)&v,  g_v);
    cudaGetSymbolAddress((void**)&xh, g_xh);
    cudaGetSymbolAddress((void**)&wh, g_wh);
    cudaGetSymbolAddress((void**)&ah, g_ah);

    cudaFuncSetAttribute(mma_gemm4, cudaFuncAttributeMaxDynamicSharedMemorySize, SMEM_DYN);

    // Fused one-time conversion, 4 float4/thread
    conv_all<<<CN4 / (256 * 4), 256>>>(x, Wq, Wk, Wv, Wo);

    // Fused Q/K/V projections (fp16 out, head layout); Q,K get the feature map.
    mma_gemm4<<<dim3(DD / BN, MM / BM, 3), 256, SMEM_DYN>>>(
        xh, wh, bq, bk, bv, nullptr, q, k, v, 1, 1, 0, /*head_layout=*/1);

    chunk_kv_mma<<<dim3(NC, BH), 128>>>();
    prefix_scan<<<dim3(2, BH), 256>>>();
    attn_mma<<<dim3(NC, BH), 128>>>();

    // Output projection (fp32 out)
    mma_gemm4<<<dim3(DD / BN, MM / BM, 1), 256, SMEM_DYN>>>(
        ah, wh + 3 * (size_t)DD * DD, bo, bo, bo, out, nullptr, nullptr, nullptr,
        0, 0, 0, /*head_layout=*/0);
}

// round 14
// speedup vs baseline: 1.0002x; 1.0002x over previous
#include <cuda_runtime.h>
#include <cuda_fp16.h>
#include <cstdint>

// Problem constants
#define BB   2
#define TT   2048
#define DD   1024
#define HH   16
#define DH   64
#define NC   32           // TT / 64 chunks
#define BH   32           // BB * HH
#define MM   4096         // BB * TT
#define EPSF 1e-6f

// GEMM tiling (round-10 proven config: BK=32, 3-stage cp.async, 2 CTAs/SM)
#define BM   128
#define BN   128
#define BK   32
#define NKB  (DD / BK)    // 32 k-stages
#define ROWB  80          // padded row stride bytes (32 fp16 + 16B pad)
#define TILEB (128 * ROWB)
#define STG   (2 * TILEB)
#define NSTG  3
#define SMEM_DYN (NSTG * STG)       // 61440 B

#define XN4 (MM * DD / 4)
#define WN4 (DD * DD / 4)
#define CN4 (XN4 + 4 * WN4)

// attention smem row stride: 72 fp16 = 144B (conflict-free LDSM)
#define SR 72

// Scratch (device globals; allocation is forbidden)
__device__ __half g_q[BH * TT * DH];        // [b,h,t,dh] fp16
__device__ __half g_k[BH * TT * DH];
__device__ __half g_v[BH * TT * DH];
__device__ __half g_kvh[BH * NC * DH * DH]; // per-chunk KV (fp16)
__device__ __half g_sh[BH * NC * DH * DH];  // exclusive-prefix S (fp16)
__device__ float  g_ks[BH * NC * DH];       // k-sum, then exclusive prefix (fp32)

// Persistent fp16 copies
__device__ __half g_xh[MM * DD];
__device__ __half g_wh[4 * DD * DD];        // Wq | Wk | Wv | Wo
__device__ __half g_ah[MM * DD];            // attention output

// ---------------------------------------------------------------------------
// helpers
// ---------------------------------------------------------------------------
__device__ __forceinline__ uint32_t smem_u32(const void* p) {
    uint32_t a;
    asm("{ .reg .u64 t; cvta.to.shared.u64 t, %1; cvt.u32.u64 %0, t; }"
        : "=r"(a) : "l"(p));
    return a;
}
__device__ __forceinline__ uint32_t packf2h(float lo, float hi) {
    __half2 h = __floats2half2_rn(lo, hi);
    return *(uint32_t*)&h;
}
__device__ __forceinline__ void mma16816(float* c, const uint32_t* a, const uint32_t* b) {
    asm volatile(
        "mma.sync.aligned.m16n8k16.row.col.f32.f16.f16.f32 "
        "{%0,%1,%2,%3}, {%4,%5,%6,%7}, {%8,%9}, {%0,%1,%2,%3};"
        : "+f"(c[0]), "+f"(c[1]), "+f"(c[2]), "+f"(c[3])
        : "r"(a[0]), "r"(a[1]), "r"(a[2]), "r"(a[3]), "r"(b[0]), "r"(b[1]));
}
__device__ __forceinline__ void ldsm4(uint32_t* r, uint32_t addr) {
    asm volatile("ldmatrix.sync.aligned.m8n8.x4.shared.b16 {%0,%1,%2,%3}, [%4];"
                 : "=r"(r[0]), "=r"(r[1]), "=r"(r[2]), "=r"(r[3]) : "r"(addr));
}
__device__ __forceinline__ void ldsm4t(uint32_t* r, uint32_t addr) {
    asm volatile("ldmatrix.sync.aligned.m8n8.x4.trans.shared.b16 {%0,%1,%2,%3}, [%4];"
                 : "=r"(r[0]), "=r"(r[1]), "=r"(r[2]), "=r"(r[3]) : "r"(addr));
}
__device__ __forceinline__ void cp16(uint32_t dst, const void* src) {
    asm volatile("cp.async.cg.shared.global [%0], [%1], 16;"
                 :: "r"(dst), "l"(src) : "memory");
}
#define CP_COMMIT() asm volatile("cp.async.commit_group;" ::: "memory")
#define CP_WAIT1()  asm volatile("cp.async.wait_group 1;"  ::: "memory")

// ---------------------------------------------------------------------------
// Fused one-time fp32 -> fp16 cast: x then Wq/Wk/Wv/Wo. Grid-stride, 4/thread.
// ---------------------------------------------------------------------------
__global__ __launch_bounds__(256) void conv_all(
    const float* __restrict__ x,
    const float* __restrict__ Wq, const float* __restrict__ Wk,
    const float* __restrict__ Wv, const float* __restrict__ Wo)
{
    const int stride = gridDim.x * 256;
    for (int i = blockIdx.x * 256 + threadIdx.x; i < CN4; i += stride) {
        const float* src;
        __half* dst;
        int j;
        if (i < XN4) {
            src = x; dst = g_xh; j = i;
        } else {
            const int t = i - XN4;
            const int w = t / WN4;
            j = t - w * WN4;
            src = (w == 0) ? Wq : (w == 1) ? Wk : (w == 2) ? Wv : Wo;
            dst = g_wh + (size_t)w * DD * DD;
        }
        float4 v = ((const float4*)src)[j];
        uint2 u;
        u.x = packf2h(v.x, v.y);
        u.y = packf2h(v.z, v.w);
        ((uint2*)dst)[j] = u;
    }
}

// ---------------------------------------------------------------------------
// fp16 tensor-core GEMM. head_layout: write fp16 to h0/h1/h2 in [b,h,t,dh];
// else write fp32 to o0 in [m][n]. BK=32, 2 CTAs/SM, cp.async 3-stage, ldmatrix.
// ---------------------------------------------------------------------------
__global__ __launch_bounds__(256, 2) void mma_gemm4(
    const __half* __restrict__ A, const __half* __restrict__ W,
    const float* __restrict__ bz0, const float* __restrict__ bz1, const float* __restrict__ bz2,
    float* __restrict__ o0,
    __half* __restrict__ h0, __half* __restrict__ h1, __half* __restrict__ h2,
    int f0, int f1, int f2, int head_layout)
{
    extern __shared__ char dsm[];

    const int z = blockIdx.z;
    const __half* B = W + (size_t)z * DD * DD;
    const float* bias = (z == 0) ? bz0 : (z == 1) ? bz1 : bz2;
    __half*      houtp = (z == 0) ? h0 : (z == 1) ? h1 : h2;
    const int    fm   = (z == 0) ? f0  : (z == 1) ? f1  : f2;

    const int tid  = threadIdx.x;
    const int wid  = tid >> 5, lane = tid & 31;
    const int m0   = blockIdx.y * BM, n0 = blockIdx.x * BN;
    const int wm   = (wid >> 2) * 64, wn = (wid & 3) * 32;
    const int g    = lane >> 2, tig = lane & 3;
    const uint32_t sb = smem_u32(dsm);

    float acc[4][4][4];
    #pragma unroll
    for (int i = 0; i < 4; i++)
        #pragma unroll
        for (int j = 0; j < 4; j++)
            #pragma unroll
            for (int q = 0; q < 4; q++) acc[i][j][q] = 0.f;

    const int srow = tid >> 1;
    const int scol = (tid & 1) * 16;
    const uint32_t doff = (uint32_t)srow * ROWB + scol * 2;

    auto issue = [&](int c, int s) {
        const uint32_t base = sb + s * STG;
        const int kb = c * BK;
        const __half* ap = A + (size_t)(m0 + srow) * DD + kb + scol;
        const __half* bp = B + (size_t)(n0 + srow) * DD + kb + scol;
        cp16(base + doff,              ap);
        cp16(base + doff + 16,         ap + 8);
        cp16(base + TILEB + doff,      bp);
        cp16(base + TILEB + doff + 16, bp + 8);
    };

    auto compute = [&](int s) {
        const uint32_t base = sb + s * STG;
        #pragma unroll
        for (int kt = 0; kt < 2; kt++) {
            const uint32_t kby = kt * 32;
            uint32_t bf[4][2];
            #pragma unroll
            for (int ntp = 0; ntp < 2; ntp++) {
                const uint32_t baddr = base + TILEB +
                    (uint32_t)(wn + ntp * 16 + ((lane >> 4) & 1) * 8 + (lane & 7)) * ROWB +
                    kby + ((lane >> 3) & 1) * 16;
                uint32_t t[4];
                ldsm4(t, baddr);
                bf[2 * ntp][0] = t[0];     bf[2 * ntp][1] = t[1];
                bf[2 * ntp + 1][0] = t[2]; bf[2 * ntp + 1][1] = t[3];
            }
            #pragma unroll
            for (int mt = 0; mt < 4; mt++) {
                const uint32_t aaddr = base +
                    (uint32_t)(wm + mt * 16 + ((lane >> 3) & 1) * 8 + (lane & 7)) * ROWB +
                    kby + ((lane >> 4) & 1) * 16;
                uint32_t af[4];
                ldsm4(af, aaddr);
                #pragma unroll
                for (int nt = 0; nt < 4; nt++)
                    mma16816(acc[mt][nt], af, bf[nt]);
            }
        }
    };

    issue(0, 0); CP_COMMIT();
    issue(1, 1); CP_COMMIT();

    for (int c = 0; c < NKB; c++) {
        CP_WAIT1();
        __syncthreads();
        compute(c % NSTG);
        if (c + 2 < NKB) issue(c + 2, (c + 2) % NSTG);
        CP_COMMIT();
    }

    const int hcol = (n0 + wn) >> 6;
    #pragma unroll
    for (int mt = 0; mt < 4; mt++) {
        const int r0 = m0 + wm + mt * 16 + g;
        #pragma unroll
        for (int nt = 0; nt < 4; nt++) {
            const int cn = n0 + wn + nt * 8 + 2 * tig;
            float v0 = acc[mt][nt][0] + bias[cn];
            float v1 = acc[mt][nt][1] + bias[cn + 1];
            float v2 = acc[mt][nt][2] + bias[cn];
            float v3 = acc[mt][nt][3] + bias[cn + 1];
            if (fm) {
                v0 = (v0 > 0.f) ? (v0 + 1.f) : expf(v0);
                v1 = (v1 > 0.f) ? (v1 + 1.f) : expf(v1);
                v2 = (v2 > 0.f) ? (v2 + 1.f) : expf(v2);
                v3 = (v3 > 0.f) ? (v3 + 1.f) : expf(v3);
            }
            if (head_layout) {
                const int b = r0 >> 11, t = r0 & (TT - 1);
                const int dh = cn & 63;
                __half* p = houtp + ((size_t)((b * HH + hcol) * TT + t)) * DH + dh;
                *(uint32_t*)p            = packf2h(v0, v1);
                *(uint32_t*)(p + 8 * DH) = packf2h(v2, v3);
            } else {
                float* p = o0 + (size_t)r0 * DD + cn;
                *(float2*)p            = make_float2(v0, v1);
                *(float2*)(p + 8 * DD) = make_float2(v2, v3);
            }
        }
    }
}

// ---------------------------------------------------------------------------
// chunk_kv via mma: KV[d][e] = sum_t K[t][d] V[t][e]  -> fp16 out
// ---------------------------------------------------------------------------
__global__ __launch_bounds__(128) void chunk_kv_mma()
{
    __shared__ __half Ks[64 * SR];
    __shared__ __half Vs[64 * SR];

    const int c = blockIdx.x, bh = blockIdx.y;
    const int tid = threadIdx.x;
    const int wid = tid >> 5, lane = tid & 31;
    const int g = lane >> 2, tig = lane & 3;
    const int wm = wid * 16;

    const __half* kp = g_k + ((size_t)bh * TT + c * 64) * DH;
    const __half* vp = g_v + ((size_t)bh * TT + c * 64) * DH;
    const int lr = tid >> 1, lc = (tid & 1) * 32;
    #pragma unroll
    for (int u = 0; u < 4; u++) {
        *(uint4*)(Ks + lr * SR + lc + u * 8) = *(const uint4*)(kp + lr * 64 + lc + u * 8);
        *(uint4*)(Vs + lr * SR + lc + u * 8) = *(const uint4*)(vp + lr * 64 + lc + u * 8);
    }
    __syncthreads();

    const uint32_t kb = smem_u32(Ks), vb = smem_u32(Vs);
    float acc[8][4];
    #pragma unroll
    for (int i = 0; i < 8; i++)
        #pragma unroll
        for (int q = 0; q < 4; q++) acc[i][q] = 0.f;

    #pragma unroll
    for (int ks = 0; ks < 4; ks++) {
        const int t0 = ks * 16;
        uint32_t ka[4];
        ldsm4t(ka, kb + (uint32_t)(t0 + ((lane >> 4) & 1) * 8 + (lane & 7)) * (SR * 2)
                     + wm * 2 + ((lane >> 3) & 1) * 16);
        #pragma unroll
        for (int ntp = 0; ntp < 4; ntp++) {
            uint32_t t[4];
            ldsm4t(t, vb + (uint32_t)(t0 + ((lane >> 3) & 1) * 8 + (lane & 7)) * (SR * 2)
                        + ntp * 32 + ((lane >> 4) & 1) * 16);
            uint32_t b0[2] = { t[0], t[1] }, b1[2] = { t[2], t[3] };
            mma16816(acc[2 * ntp],     ka, b0);
            mma16816(acc[2 * ntp + 1], ka, b1);
        }
    }

    __half* kvout = g_kvh + ((size_t)bh * NC + c) * 4096;
    #pragma unroll
    for (int nt = 0; nt < 8; nt++) {
        const int col = nt * 8 + 2 * tig;
        *(uint32_t*)(kvout + (wm + g) * 64 + col)     = packf2h(acc[nt][0], acc[nt][1]);
        *(uint32_t*)(kvout + (wm + g + 8) * 64 + col) = packf2h(acc[nt][2], acc[nt][3]);
    }

    if (tid < 64) {
        float s = 0.f;
        #pragma unroll 8
        for (int t = 0; t < 64; t++) s += __half2float(Ks[t * SR + tid]);
        g_ks[((size_t)bh * NC + c) * 64 + tid] = s;
    }
}

// ---------------------------------------------------------------------------
// Exclusive prefix scan across chunks; fp16 in (g_kvh), fp16 out (g_sh).
// 4 pair-positions per thread (8 halves); register-prefetched (MLP up to 128).
// grid (2, BH) x 256 threads.
// ---------------------------------------------------------------------------
__global__ __launch_bounds__(256) void prefix_scan()
{
    const int bh = blockIdx.y;
    const int t0 = blockIdx.x * 256 + threadIdx.x;   // 0..511
    const __half* basep = g_kvh + (size_t)bh * NC * 4096;
    __half* outbp = g_sh + (size_t)bh * NC * 4096;

    #pragma unroll
    for (int u = 0; u < 4; u++) {
        const int p2 = t0 + u * 512;                 // pair index 0..2047
        const __half* base = basep + p2 * 2;
        __half* outp = outbp + p2 * 2;
        __half2 v[NC];
        #pragma unroll
        for (int c = 0; c < NC; c++) v[c] = *(const __half2*)(base + c * 4096);
        float2 run = make_float2(0.f, 0.f);
        #pragma unroll
        for (int c = 0; c < NC; c++) {
            *(__half2*)(outp + c * 4096) = __floats2half2_rn(run.x, run.y);
            float2 f = __half22float2(v[c]);
            run.x += f.x; run.y += f.y;
        }
    }

    if (blockIdx.x == 0 && threadIdx.x < 64) {
        float w[NC];
        float* kbp = g_ks + (size_t)bh * NC * 64 + threadIdx.x;
        #pragma unroll
        for (int c = 0; c < NC; c++) w[c] = kbp[c * 64];
        float r2 = 0.f;
        #pragma unroll
        for (int c = 0; c < NC; c++) {
            kbp[c * 64] = r2;
            r2 += w[c];
        }
    }
}

// ---------------------------------------------------------------------------
// Attention chunk via mma: A = mask(QK^T); out = (A V + Q S) / (rowsum(A)+Qz)
// Writes fp16 g_ah for the O-gemm.
// ---------------------------------------------------------------------------
__global__ __launch_bounds__(128) void attn_mma()
{
    __shared__ __half Qs[64 * SR];
    __shared__ __half Ks[64 * SR];   // K, then reused as A
    __shared__ __half Vs[64 * SR];
    __shared__ __half Ss[64 * SR];
    __shared__ float  zs[64];

    const int c = blockIdx.x, bh = blockIdx.y;
    const int tid = threadIdx.x;
    const int wid = tid >> 5, lane = tid & 31;
    const int g = lane >> 2, tig = lane & 3;
    const int wm = wid * 16;

    const __half* qp = g_q + ((size_t)bh * TT + c * 64) * DH;
    const __half* kp = g_k + ((size_t)bh * TT + c * 64) * DH;
    const __half* vp = g_v + ((size_t)bh * TT + c * 64) * DH;
    const __half* sp = g_sh + ((size_t)bh * NC + c) * 4096;

    const int lr = tid >> 1, lc = (tid & 1) * 32;
    #pragma unroll
    for (int u = 0; u < 4; u++) {
        *(uint4*)(Qs + lr * SR + lc + u * 8) = *(const uint4*)(qp + lr * 64 + lc + u * 8);
        *(uint4*)(Ks + lr * SR + lc + u * 8) = *(const uint4*)(kp + lr * 64 + lc + u * 8);
        *(uint4*)(Vs + lr * SR + lc + u * 8) = *(const uint4*)(vp + lr * 64 + lc + u * 8);
        *(uint4*)(Ss + lr * SR + lc + u * 8) = *(const uint4*)(sp + lr * 64 + lc + u * 8);
    }
    if (tid < 64) zs[tid] = g_ks[((size_t)bh * NC + c) * 64 + tid];
    __syncthreads();

    const uint32_t qb = smem_u32(Qs), kb = smem_u32(Ks);
    const uint32_t vb = smem_u32(Vs), sb = smem_u32(Ss);

    // ---- GEMM1: A = Q K^T ----
    float aa[8][4];
    #pragma unroll
    for (int i = 0; i < 8; i++)
        #pragma unroll
        for (int q = 0; q < 4; q++) aa[i][q] = 0.f;

    #pragma unroll
    for (int ks = 0; ks < 4; ks++) {
        const uint32_t kby = ks * 32;
        uint32_t qa[4];
        ldsm4(qa, qb + (uint32_t)(wm + ((lane >> 3) & 1) * 8 + (lane & 7)) * (SR * 2)
                    + kby + ((lane >> 4) & 1) * 16);
        #pragma unroll
        for (int ntp = 0; ntp < 4; ntp++) {
            uint32_t t[4];
            ldsm4(t, kb + (uint32_t)(ntp * 16 + ((lane >> 4) & 1) * 8 + (lane & 7)) * (SR * 2)
                       + kby + ((lane >> 3) & 1) * 16);
            uint32_t b0[2] = { t[0], t[1] }, b1[2] = { t[2], t[3] };
            mma16816(aa[2 * ntp],     qa, b0);
            mma16816(aa[2 * ntp + 1], qa, b1);
        }
    }

    // mask + rowsum
    const int r0 = wm + g, r1 = r0 + 8;
    float rs0 = 0.f, rs1 = 0.f;
    #pragma unroll
    for (int nt = 0; nt < 8; nt++) {
        const int c0 = nt * 8 + 2 * tig, c1 = c0 + 1;
        if (c0 > r0) aa[nt][0] = 0.f;
        if (c1 > r0) aa[nt][1] = 0.f;
        if (c0 > r1) aa[nt][2] = 0.f;
        if (c1 > r1) aa[nt][3] = 0.f;
        rs0 += aa[nt][0] + aa[nt][1];
        rs1 += aa[nt][2] + aa[nt][3];
    }
    #pragma unroll
    for (int off = 1; off < 4; off <<= 1) {
        rs0 += __shfl_xor_sync(0xffffffffu, rs0, off);
        rs1 += __shfl_xor_sync(0xffffffffu, rs1, off);
    }

    // qz
    float qz0 = 0.f, qz1 = 0.f;
    #pragma unroll 8
    for (int d2 = 0; d2 < 32; d2++) {
        float2 z2 = *(const float2*)(zs + 2 * d2);
        float2 q0 = __half22float2(*(const __half2*)(Qs + r0 * SR + 2 * d2));
        float2 q1 = __half22float2(*(const __half2*)(Qs + r1 * SR + 2 * d2));
        qz0 += q0.x * z2.x + q0.y * z2.y;
        qz1 += q1.x * z2.x + q1.y * z2.y;
    }

    // write masked A (fp16) into Ks
    __syncthreads();
    #pragma unroll
    for (int nt = 0; nt < 8; nt++) {
        const int col = nt * 8 + 2 * tig;
        *(uint32_t*)(Ks + r0 * SR + col) = packf2h(aa[nt][0], aa[nt][1]);
        *(uint32_t*)(Ks + r1 * SR + col) = packf2h(aa[nt][2], aa[nt][3]);
    }
    __syncthreads();

    // ---- GEMM2: out = A V + GEMM3: out += Q S ----
    float oc[8][4];
    #pragma unroll
    for (int i = 0; i < 8; i++)
        #pragma unroll
        for (int q = 0; q < 4; q++) oc[i][q] = 0.f;

    #pragma unroll
    for (int ks = 0; ks < 4; ks++) {
        const uint32_t kby = ks * 32;
        uint32_t af[4];
        ldsm4(af, kb + (uint32_t)(wm + ((lane >> 3) & 1) * 8 + (lane & 7)) * (SR * 2)
                    + kby + ((lane >> 4) & 1) * 16);
        #pragma unroll
        for (int ntp = 0; ntp < 4; ntp++) {
            uint32_t t[4];
            ldsm4t(t, vb + (uint32_t)(ks * 16 + ((lane >> 3) & 1) * 8 + (lane & 7)) * (SR * 2)
                        + ntp * 32 + ((lane >> 4) & 1) * 16);
            uint32_t b0[2] = { t[0], t[1] }, b1[2] = { t[2], t[3] };
            mma16816(oc[2 * ntp],     af, b0);
            mma16816(oc[2 * ntp + 1], af, b1);
        }
    }
    #pragma unroll
    for (int ks = 0; ks < 4; ks++) {
        const uint32_t kby = ks * 32;
        uint32_t qa[4];
        ldsm4(qa, qb + (uint32_t)(wm + ((lane >> 3) & 1) * 8 + (lane & 7)) * (SR * 2)
                    + kby + ((lane >> 4) & 1) * 16);
        #pragma unroll
        for (int ntp = 0; ntp < 4; ntp++) {
            uint32_t t[4];
            ldsm4t(t, sb + (uint32_t)(ks * 16 + ((lane >> 3) & 1) * 8 + (lane & 7)) * (SR * 2)
                        + ntp * 32 + ((lane >> 4) & 1) * 16);
            uint32_t b0[2] = { t[0], t[1] }, b1[2] = { t[2], t[3] };
            mma16816(oc[2 * ntp],     qa, b0);
            mma16816(oc[2 * ntp + 1], qa, b1);
        }
    }

    const float inv0 = 1.f / fmaxf(rs0 + qz0, EPSF);
    const float inv1 = 1.f / fmaxf(rs1 + qz1, EPSF);
    const int b = bh >> 4, h = bh & 15;
    __half* p0 = g_ah + ((size_t)(b * TT + c * 64 + r0)) * DD + h * 64;
    __half* p1 = g_ah + ((size_t)(b * TT + c * 64 + r1)) * DD + h * 64;
    #pragma unroll
    for (int nt = 0; nt < 8; nt++) {
        const int col = nt * 8 + 2 * tig;
        *(uint32_t*)(p0 + col) = packf2h(oc[nt][0] * inv0, oc[nt][1] * inv0);
        *(uint32_t*)(p1 + col) = packf2h(oc[nt][2] * inv1, oc[nt][3] * inv1);
    }
}

// ---------------------------------------------------------------------------
extern "C" void kernel_launch(void* const* d_in, const int* in_sizes, int n_in,
                              void* d_out, int out_size)
{
    const float* x  = (const float*)d_in[0];
    const float* Wq = (const float*)d_in[1];
    const float* bq = (const float*)d_in[2];
    const float* Wk = (const float*)d_in[3];
    const float* bk = (const float*)d_in[4];
    const float* Wv = (const float*)d_in[5];
    const float* bv = (const float*)d_in[6];
    const float* Wo = (const float*)d_in[7];
    const float* bo = (const float*)d_in[8];
    float* out = (float*)d_out;

    __half *q, *k, *v, *xh, *wh, *ah;
    cudaGetSymbolAddress((void**)&q,  g_q);
    cudaGetSymbolAddress((void**)&k,  g_k);
    cudaGetSymbolAddress((void**)&v,  g_v);
    cudaGetSymbolAddress((void**)&xh, g_xh);
    cudaGetSymbolAddress((void**)&wh, g_wh);
    cudaGetSymbolAddress((void**)&ah, g_ah);

    cudaFuncSetAttribute(mma_gemm4, cudaFuncAttributeMaxDynamicSharedMemorySize, SMEM_DYN);

    // Fused one-time conversion, 4 float4/thread
    conv_all<<<CN4 / (256 * 4), 256>>>(x, Wq, Wk, Wv, Wo);

    // Fused Q/K/V projections (fp16 out, head layout); Q,K get the feature map.
    mma_gemm4<<<dim3(DD / BN, MM / BM, 3), 256, SMEM_DYN>>>(
        xh, wh, bq, bk, bv, nullptr, q, k, v, 1, 1, 0, /*head_layout=*/1);

    chunk_kv_mma<<<dim3(NC, BH), 128>>>();
    prefix_scan<<<dim3(2, BH), 256>>>();
    attn_mma<<<dim3(NC, BH), 128>>>();

    // Output projection (fp32 out)
    mma_gemm4<<<dim3(DD / BN, MM / BM, 1), 256, SMEM_DYN>>>(
        ah, wh + 3 * (size_t)DD * DD, bo, bo, bo, out, nullptr, nullptr, nullptr,
        0, 0, 0, /*head_layout=*/0);
}

// round 15
// speedup vs baseline: 1.0229x; 1.0227x over previous
#include <cuda_runtime.h>
#include <cuda_fp16.h>
#include <cstdint>

// Problem constants
#define BB   2
#define TT   2048
#define DD   1024
#define HH   16
#define DH   64
#define NC   32           // TT / 64 chunks
#define BH   32           // BB * HH
#define MM   4096         // BB * TT
#define EPSF 1e-6f

// GEMM tiling (round-10 proven config: BK=32, 3-stage cp.async, 2 CTAs/SM)
#define BM   128
#define BN   128
#define BK   32
#define NKB  (DD / BK)    // 32 k-stages
#define ROWB  80          // padded row stride bytes (32 fp16 + 16B pad)
#define TILEB (128 * ROWB)
#define STG   (2 * TILEB)
#define NSTG  3
#define SMEM_DYN (NSTG * STG)       // 61440 B

#define XN4 (MM * DD / 4)
#define WN4 (DD * DD / 4)

// attention smem row stride: 72 fp16 = 144B (conflict-free LDSM)
#define SR 72

// Scratch (device globals; allocation is forbidden)
__device__ __half g_q[BH * TT * DH];        // [b,h,t,dh] fp16
__device__ __half g_k[BH * TT * DH];
__device__ __half g_v[BH * TT * DH];
__device__ __half g_kvh[BH * NC * DH * DH]; // per-chunk KV (fp16)
__device__ __half g_sh[BH * NC * DH * DH];  // exclusive-prefix S (fp16)
__device__ float  g_ks[BH * NC * DH];       // k-sum, then exclusive prefix (fp32)

// Persistent fp16 copies
__device__ __half g_xh[MM * DD];
__device__ __half g_wh[4 * DD * DD];        // Wq | Wk | Wv | Wo
__device__ __half g_ah[MM * DD];            // attention output

// ---------------------------------------------------------------------------
// helpers
// ---------------------------------------------------------------------------
__device__ __forceinline__ uint32_t smem_u32(const void* p) {
    uint32_t a;
    asm("{ .reg .u64 t; cvta.to.shared.u64 t, %1; cvt.u32.u64 %0, t; }"
        : "=r"(a) : "l"(p));
    return a;
}
__device__ __forceinline__ uint32_t packf2h(float lo, float hi) {
    __half2 h = __floats2half2_rn(lo, hi);
    return *(uint32_t*)&h;
}
__device__ __forceinline__ void mma16816(float* c, const uint32_t* a, const uint32_t* b) {
    asm volatile(
        "mma.sync.aligned.m16n8k16.row.col.f32.f16.f16.f32 "
        "{%0,%1,%2,%3}, {%4,%5,%6,%7}, {%8,%9}, {%0,%1,%2,%3};"
        : "+f"(c[0]), "+f"(c[1]), "+f"(c[2]), "+f"(c[3])
        : "r"(a[0]), "r"(a[1]), "r"(a[2]), "r"(a[3]), "r"(b[0]), "r"(b[1]));
}
__device__ __forceinline__ void ldsm4(uint32_t* r, uint32_t addr) {
    asm volatile("ldmatrix.sync.aligned.m8n8.x4.shared.b16 {%0,%1,%2,%3}, [%4];"
                 : "=r"(r[0]), "=r"(r[1]), "=r"(r[2]), "=r"(r[3]) : "r"(addr));
}
__device__ __forceinline__ void ldsm4t(uint32_t* r, uint32_t addr) {
    asm volatile("ldmatrix.sync.aligned.m8n8.x4.trans.shared.b16 {%0,%1,%2,%3}, [%4];"
                 : "=r"(r[0]), "=r"(r[1]), "=r"(r[2]), "=r"(r[3]) : "r"(addr));
}
__device__ __forceinline__ void cp16(uint32_t dst, const void* src) {
    asm volatile("cp.async.cg.shared.global [%0], [%1], 16;"
                 :: "r"(dst), "l"(src) : "memory");
}
#define CP_COMMIT() asm volatile("cp.async.commit_group;" ::: "memory")
#define CP_WAIT1()  asm volatile("cp.async.wait_group 1;"  ::: "memory")
#define CP_WAIT0()  asm volatile("cp.async.wait_group 0;"  ::: "memory")

// ---------------------------------------------------------------------------
// Fused one-time fp32 -> fp16 cast: x then Wq/Wk/Wv/Wo  (round-10 config)
// ---------------------------------------------------------------------------
__global__ __launch_bounds__(256) void conv_all(
    const float* __restrict__ x,
    const float* __restrict__ Wq, const float* __restrict__ Wk,
    const float* __restrict__ Wv, const float* __restrict__ Wo)
{
    const int i = blockIdx.x * 256 + threadIdx.x;
    const float* src;
    __half* dst;
    int j;
    if (i < XN4) {
        src = x; dst = g_xh; j = i;
    } else {
        const int t = i - XN4;
        const int w = t / WN4;
        j = t - w * WN4;
        src = (w == 0) ? Wq : (w == 1) ? Wk : (w == 2) ? Wv : Wo;
        dst = g_wh + (size_t)w * DD * DD;
    }
    float4 v = ((const float4*)src)[j];
    uint2 u;
    u.x = packf2h(v.x, v.y);
    u.y = packf2h(v.z, v.w);
    ((uint2*)dst)[j] = u;
}

// ---------------------------------------------------------------------------
// fp16 tensor-core GEMM. head_layout: write fp16 to h0/h1/h2 in [b,h,t,dh];
// else write fp32 to o0 in [m][n]. BK=32, 2 CTAs/SM, cp.async 3-stage, ldmatrix.
// ---------------------------------------------------------------------------
__global__ __launch_bounds__(256, 2) void mma_gemm4(
    const __half* __restrict__ A, const __half* __restrict__ W,
    const float* __restrict__ bz0, const float* __restrict__ bz1, const float* __restrict__ bz2,
    float* __restrict__ o0,
    __half* __restrict__ h0, __half* __restrict__ h1, __half* __restrict__ h2,
    int f0, int f1, int f2, int head_layout)
{
    extern __shared__ char dsm[];

    const int z = blockIdx.z;
    const __half* B = W + (size_t)z * DD * DD;
    const float* bias = (z == 0) ? bz0 : (z == 1) ? bz1 : bz2;
    __half*      houtp = (z == 0) ? h0 : (z == 1) ? h1 : h2;
    const int    fm   = (z == 0) ? f0  : (z == 1) ? f1  : f2;

    const int tid  = threadIdx.x;
    const int wid  = tid >> 5, lane = tid & 31;
    const int m0   = blockIdx.y * BM, n0 = blockIdx.x * BN;
    const int wm   = (wid >> 2) * 64, wn = (wid & 3) * 32;
    const int g    = lane >> 2, tig = lane & 3;
    const uint32_t sb = smem_u32(dsm);

    float acc[4][4][4];
    #pragma unroll
    for (int i = 0; i < 4; i++)
        #pragma unroll
        for (int j = 0; j < 4; j++)
            #pragma unroll
            for (int q = 0; q < 4; q++) acc[i][j][q] = 0.f;

    const int srow = tid >> 1;
    const int scol = (tid & 1) * 16;
    const uint32_t doff = (uint32_t)srow * ROWB + scol * 2;

    auto issue = [&](int c, int s) {
        const uint32_t base = sb + s * STG;
        const int kb = c * BK;
        const __half* ap = A + (size_t)(m0 + srow) * DD + kb + scol;
        const __half* bp = B + (size_t)(n0 + srow) * DD + kb + scol;
        cp16(base + doff,              ap);
        cp16(base + doff + 16,         ap + 8);
        cp16(base + TILEB + doff,      bp);
        cp16(base + TILEB + doff + 16, bp + 8);
    };

    auto compute = [&](int s) {
        const uint32_t base = sb + s * STG;
        #pragma unroll
        for (int kt = 0; kt < 2; kt++) {
            const uint32_t kby = kt * 32;
            uint32_t bf[4][2];
            #pragma unroll
            for (int ntp = 0; ntp < 2; ntp++) {
                const uint32_t baddr = base + TILEB +
                    (uint32_t)(wn + ntp * 16 + ((lane >> 4) & 1) * 8 + (lane & 7)) * ROWB +
                    kby + ((lane >> 3) & 1) * 16;
                uint32_t t[4];
                ldsm4(t, baddr);
                bf[2 * ntp][0] = t[0];     bf[2 * ntp][1] = t[1];
                bf[2 * ntp + 1][0] = t[2]; bf[2 * ntp + 1][1] = t[3];
            }
            #pragma unroll
            for (int mt = 0; mt < 4; mt++) {
                const uint32_t aaddr = base +
                    (uint32_t)(wm + mt * 16 + ((lane >> 3) & 1) * 8 + (lane & 7)) * ROWB +
                    kby + ((lane >> 4) & 1) * 16;
                uint32_t af[4];
                ldsm4(af, aaddr);
                #pragma unroll
                for (int nt = 0; nt < 4; nt++)
                    mma16816(acc[mt][nt], af, bf[nt]);
            }
        }
    };

    issue(0, 0); CP_COMMIT();
    issue(1, 1); CP_COMMIT();

    for (int c = 0; c < NKB; c++) {
        CP_WAIT1();
        __syncthreads();
        compute(c % NSTG);
        if (c + 2 < NKB) issue(c + 2, (c + 2) % NSTG);
        CP_COMMIT();
    }

    const int hcol = (n0 + wn) >> 6;
    #pragma unroll
    for (int mt = 0; mt < 4; mt++) {
        const int r0 = m0 + wm + mt * 16 + g;
        #pragma unroll
        for (int nt = 0; nt < 4; nt++) {
            const int cn = n0 + wn + nt * 8 + 2 * tig;
            float v0 = acc[mt][nt][0] + bias[cn];
            float v1 = acc[mt][nt][1] + bias[cn + 1];
            float v2 = acc[mt][nt][2] + bias[cn];
            float v3 = acc[mt][nt][3] + bias[cn + 1];
            if (fm) {
                v0 = (v0 > 0.f) ? (v0 + 1.f) : expf(v0);
                v1 = (v1 > 0.f) ? (v1 + 1.f) : expf(v1);
                v2 = (v2 > 0.f) ? (v2 + 1.f) : expf(v2);
                v3 = (v3 > 0.f) ? (v3 + 1.f) : expf(v3);
            }
            if (head_layout) {
                const int b = r0 >> 11, t = r0 & (TT - 1);
                const int dh = cn & 63;
                __half* p = houtp + ((size_t)((b * HH + hcol) * TT + t)) * DH + dh;
                *(uint32_t*)p            = packf2h(v0, v1);
                *(uint32_t*)(p + 8 * DH) = packf2h(v2, v3);
            } else {
                float* p = o0 + (size_t)r0 * DD + cn;
                *(float2*)p            = make_float2(v0, v1);
                *(float2*)(p + 8 * DD) = make_float2(v2, v3);
            }
        }
    }
}

// ---------------------------------------------------------------------------
// chunk_kv via mma: KV[d][e] = sum_t K[t][d] V[t][e]  -> fp16 out
// ---------------------------------------------------------------------------
__global__ __launch_bounds__(128) void chunk_kv_mma()
{
    __shared__ __half Ks[64 * SR];
    __shared__ __half Vs[64 * SR];

    const int c = blockIdx.x, bh = blockIdx.y;
    const int tid = threadIdx.x;
    const int wid = tid >> 5, lane = tid & 31;
    const int g = lane >> 2, tig = lane & 3;
    const int wm = wid * 16;

    const __half* kp = g_k + ((size_t)bh * TT + c * 64) * DH;
    const __half* vp = g_v + ((size_t)bh * TT + c * 64) * DH;
    const int lr = tid >> 1, lc = (tid & 1) * 32;
    #pragma unroll
    for (int u = 0; u < 4; u++) {
        *(uint4*)(Ks + lr * SR + lc + u * 8) = *(const uint4*)(kp + lr * 64 + lc + u * 8);
        *(uint4*)(Vs + lr * SR + lc + u * 8) = *(const uint4*)(vp + lr * 64 + lc + u * 8);
    }
    __syncthreads();

    const uint32_t kb = smem_u32(Ks), vb = smem_u32(Vs);
    float acc[8][4];
    #pragma unroll
    for (int i = 0; i < 8; i++)
        #pragma unroll
        for (int q = 0; q < 4; q++) acc[i][q] = 0.f;

    #pragma unroll
    for (int ks = 0; ks < 4; ks++) {
        const int t0 = ks * 16;
        uint32_t ka[4];
        ldsm4t(ka, kb + (uint32_t)(t0 + ((lane >> 4) & 1) * 8 + (lane & 7)) * (SR * 2)
                     + wm * 2 + ((lane >> 3) & 1) * 16);
        #pragma unroll
        for (int ntp = 0; ntp < 4; ntp++) {
            uint32_t t[4];
            ldsm4t(t, vb + (uint32_t)(t0 + ((lane >> 3) & 1) * 8 + (lane & 7)) * (SR * 2)
                        + ntp * 32 + ((lane >> 4) & 1) * 16);
            uint32_t b0[2] = { t[0], t[1] }, b1[2] = { t[2], t[3] };
            mma16816(acc[2 * ntp],     ka, b0);
            mma16816(acc[2 * ntp + 1], ka, b1);
        }
    }

    __half* kvout = g_kvh + ((size_t)bh * NC + c) * 4096;
    #pragma unroll
    for (int nt = 0; nt < 8; nt++) {
        const int col = nt * 8 + 2 * tig;
        *(uint32_t*)(kvout + (wm + g) * 64 + col)     = packf2h(acc[nt][0], acc[nt][1]);
        *(uint32_t*)(kvout + (wm + g + 8) * 64 + col) = packf2h(acc[nt][2], acc[nt][3]);
    }

    if (tid < 64) {
        float s = 0.f;
        #pragma unroll 8
        for (int t = 0; t < 64; t++) s += __half2float(Ks[t * SR + tid]);
        g_ks[((size_t)bh * NC + c) * 64 + tid] = s;
    }
}

// ---------------------------------------------------------------------------
// Exclusive prefix scan across chunks; fp16 in (g_kvh), fp16 out (g_sh).
// 2 adjacent positions per thread (__half2); register-prefetched (MLP=32).
// grid (8, BH) x 256 threads.  (round-10 proven config)
// ---------------------------------------------------------------------------
__global__ __launch_bounds__(256) void prefix_scan()
{
    const int bh = blockIdx.y;
    const int p2 = blockIdx.x * 256 + threadIdx.x;   // 0..2047 (pairs)
    const __half* base = g_kvh + (size_t)bh * NC * 4096 + p2 * 2;
    __half* outp = g_sh + (size_t)bh * NC * 4096 + p2 * 2;

    __half2 v[NC];
    #pragma unroll
    for (int c = 0; c < NC; c++) v[c] = *(const __half2*)(base + c * 4096);
    float2 run = make_float2(0.f, 0.f);
    #pragma unroll
    for (int c = 0; c < NC; c++) {
        *(__half2*)(outp + c * 4096) = __floats2half2_rn(run.x, run.y);
        float2 f = __half22float2(v[c]);
        run.x += f.x; run.y += f.y;
    }

    if (blockIdx.x == 0 && threadIdx.x < 64) {
        float w[NC];
        float* kbp = g_ks + (size_t)bh * NC * 64 + threadIdx.x;
        #pragma unroll
        for (int c = 0; c < NC; c++) w[c] = kbp[c * 64];
        float r2 = 0.f;
        #pragma unroll
        for (int c = 0; c < NC; c++) {
            kbp[c * 64] = r2;
            r2 += w[c];
        }
    }
}

// ---------------------------------------------------------------------------
// Attention chunk via mma: A = mask(QK^T); out = (A V + Q S) / (rowsum(A)+Qz)
// Q/K load synchronously; V/S prefetch via cp.async overlapped with GEMM1.
// Writes fp16 g_ah for the O-gemm.
// ---------------------------------------------------------------------------
__global__ __launch_bounds__(128) void attn_mma()
{
    __shared__ __half Qs[64 * SR];
    __shared__ __half Ks[64 * SR];   // K, then reused as A
    __shared__ __half Vs[64 * SR];
    __shared__ __half Ss[64 * SR];
    __shared__ float  zs[64];

    const int c = blockIdx.x, bh = blockIdx.y;
    const int tid = threadIdx.x;
    const int wid = tid >> 5, lane = tid & 31;
    const int g = lane >> 2, tig = lane & 3;
    const int wm = wid * 16;

    const __half* qp = g_q + ((size_t)bh * TT + c * 64) * DH;
    const __half* kp = g_k + ((size_t)bh * TT + c * 64) * DH;
    const __half* vp = g_v + ((size_t)bh * TT + c * 64) * DH;
    const __half* sp = g_sh + ((size_t)bh * NC + c) * 4096;

    const int lr = tid >> 1, lc = (tid & 1) * 32;
    const uint32_t vsm = smem_u32(Vs), ssm = smem_u32(Ss);
    // async prefetch of V and S (first used after the A-write barrier)
    #pragma unroll
    for (int u = 0; u < 2; u++) {
        const uint32_t so = (uint32_t)lr * (SR * 2) + (lc + u * 16) * 2;
        cp16(vsm + so,      vp + lr * 64 + lc + u * 16);
        cp16(vsm + so + 16, vp + lr * 64 + lc + u * 16 + 8);
        cp16(ssm + so,      sp + lr * 64 + lc + u * 16);
        cp16(ssm + so + 16, sp + lr * 64 + lc + u * 16 + 8);
    }
    CP_COMMIT();
    // synchronous Q/K loads (needed for GEMM1 immediately)
    #pragma unroll
    for (int u = 0; u < 4; u++) {
        *(uint4*)(Qs + lr * SR + lc + u * 8) = *(const uint4*)(qp + lr * 64 + lc + u * 8);
        *(uint4*)(Ks + lr * SR + lc + u * 8) = *(const uint4*)(kp + lr * 64 + lc + u * 8);
    }
    if (tid < 64) zs[tid] = g_ks[((size_t)bh * NC + c) * 64 + tid];
    __syncthreads();

    const uint32_t qb = smem_u32(Qs), kb = smem_u32(Ks);
    const uint32_t vb = vsm, sb = ssm;

    // ---- GEMM1: A = Q K^T ----
    float aa[8][4];
    #pragma unroll
    for (int i = 0; i < 8; i++)
        #pragma unroll
        for (int q = 0; q < 4; q++) aa[i][q] = 0.f;

    #pragma unroll
    for (int ks = 0; ks < 4; ks++) {
        const uint32_t kby = ks * 32;
        uint32_t qa[4];
        ldsm4(qa, qb + (uint32_t)(wm + ((lane >> 3) & 1) * 8 + (lane & 7)) * (SR * 2)
                    + kby + ((lane >> 4) & 1) * 16);
        #pragma unroll
        for (int ntp = 0; ntp < 4; ntp++) {
            uint32_t t[4];
            ldsm4(t, kb + (uint32_t)(ntp * 16 + ((lane >> 4) & 1) * 8 + (lane & 7)) * (SR * 2)
                       + kby + ((lane >> 3) & 1) * 16);
            uint32_t b0[2] = { t[0], t[1] }, b1[2] = { t[2], t[3] };
            mma16816(aa[2 * ntp],     qa, b0);
            mma16816(aa[2 * ntp + 1], qa, b1);
        }
    }

    // mask + rowsum
    const int r0 = wm + g, r1 = r0 + 8;
    float rs0 = 0.f, rs1 = 0.f;
    #pragma unroll
    for (int nt = 0; nt < 8; nt++) {
        const int c0 = nt * 8 + 2 * tig, c1 = c0 + 1;
        if (c0 > r0) aa[nt][0] = 0.f;
        if (c1 > r0) aa[nt][1] = 0.f;
        if (c0 > r1) aa[nt][2] = 0.f;
        if (c1 > r1) aa[nt][3] = 0.f;
        rs0 += aa[nt][0] + aa[nt][1];
        rs1 += aa[nt][2] + aa[nt][3];
    }
    #pragma unroll
    for (int off = 1; off < 4; off <<= 1) {
        rs0 += __shfl_xor_sync(0xffffffffu, rs0, off);
        rs1 += __shfl_xor_sync(0xffffffffu, rs1, off);
    }

    // qz
    float qz0 = 0.f, qz1 = 0.f;
    #pragma unroll 8
    for (int d2 = 0; d2 < 32; d2++) {
        float2 z2 = *(const float2*)(zs + 2 * d2);
        float2 q0 = __half22float2(*(const __half2*)(Qs + r0 * SR + 2 * d2));
        float2 q1 = __half22float2(*(const __half2*)(Qs + r1 * SR + 2 * d2));
        qz0 += q0.x * z2.x + q0.y * z2.y;
        qz1 += q1.x * z2.x + q1.y * z2.y;
    }

    // write masked A (fp16) into Ks
    __syncthreads();
    #pragma unroll
    for (int nt = 0; nt < 8; nt++) {
        const int col = nt * 8 + 2 * tig;
        *(uint32_t*)(Ks + r0 * SR + col) = packf2h(aa[nt][0], aa[nt][1]);
        *(uint32_t*)(Ks + r1 * SR + col) = packf2h(aa[nt][2], aa[nt][3]);
    }
    CP_WAIT0();          // V/S prefetch complete (per-thread)
    __syncthreads();     // publish A + V/S to all threads

    // ---- GEMM2: out = A V + GEMM3: out += Q S ----
    float oc[8][4];
    #pragma unroll
    for (int i = 0; i < 8; i++)
        #pragma unroll
        for (int q = 0; q < 4; q++) oc[i][q] = 0.f;

    #pragma unroll
    for (int ks = 0; ks < 4; ks++) {
        const uint32_t kby = ks * 32;
        uint32_t af[4];
        ldsm4(af, kb + (uint32_t)(wm + ((lane >> 3) & 1) * 8 + (lane & 7)) * (SR * 2)
                    + kby + ((lane >> 4) & 1) * 16);
        #pragma unroll
        for (int ntp = 0; ntp < 4; ntp++) {
            uint32_t t[4];
            ldsm4t(t, vb + (uint32_t)(ks * 16 + ((lane >> 3) & 1) * 8 + (lane & 7)) * (SR * 2)
                        + ntp * 32 + ((lane >> 4) & 1) * 16);
            uint32_t b0[2] = { t[0], t[1] }, b1[2] = { t[2], t[3] };
            mma16816(oc[2 * ntp],     af, b0);
            mma16816(oc[2 * ntp + 1], af, b1);
        }
    }
    #pragma unroll
    for (int ks = 0; ks < 4; ks++) {
        const uint32_t kby = ks * 32;
        uint32_t qa[4];
        ldsm4(qa, qb + (uint32_t)(wm + ((lane >> 3) & 1) * 8 + (lane & 7)) * (SR * 2)
                    + kby + ((lane >> 4) & 1) * 16);
        #pragma unroll
        for (int ntp = 0; ntp < 4; ntp++) {
            uint32_t t[4];
            ldsm4t(t, sb + (uint32_t)(ks * 16 + ((lane >> 3) & 1) * 8 + (lane & 7)) * (SR * 2)
                        + ntp * 32 + ((lane >> 4) & 1) * 16);
            uint32_t b0[2] = { t[0], t[1] }, b1[2] = { t[2], t[3] };
            mma16816(oc[2 * ntp],     qa, b0);
            mma16816(oc[2 * ntp + 1], qa, b1);
        }
    }

    const float inv0 = 1.f / fmaxf(rs0 + qz0, EPSF);
    const float inv1 = 1.f / fmaxf(rs1 + qz1, EPSF);
    const int b = bh >> 4, h = bh & 15;
    __half* p0 = g_ah + ((size_t)(b * TT + c * 64 + r0)) * DD + h * 64;
    __half* p1 = g_ah + ((size_t)(b * TT + c * 64 + r1)) * DD + h * 64;
    #pragma unroll
    for (int nt = 0; nt < 8; nt++) {
        const int col = nt * 8 + 2 * tig;
        *(uint32_t*)(p0 + col) = packf2h(oc[nt][0] * inv0, oc[nt][1] * inv0);
        *(uint32_t*)(p1 + col) = packf2h(oc[nt][2] * inv1, oc[nt][3] * inv1);
    }
}

// ---------------------------------------------------------------------------
extern "C" void kernel_launch(void* const* d_in, const int* in_sizes, int n_in,
                              void* d_out, int out_size)
{
    const float* x  = (const float*)d_in[0];
    const float* Wq = (const float*)d_in[1];
    const float* bq = (const float*)d_in[2];
    const float* Wk = (const float*)d_in[3];
    const float* bk = (const float*)d_in[4];
    const float* Wv = (const float*)d_in[5];
    const float* bv = (const float*)d_in[6];
    const float* Wo = (const float*)d_in[7];
    const float* bo = (const float*)d_in[8];
    float* out = (float*)d_out;

    __half *q, *k, *v, *xh, *wh, *ah;
    cudaGetSymbolAddress((void**)&q,  g_q);
    cudaGetSymbolAddress((void**)&k,  g_k);
    cudaGetSymbolAddress((void**)&v,  g_v);
    cudaGetSymbolAddress((void**)&xh, g_xh);
    cudaGetSymbolAddress((void**)&wh, g_wh);
    cudaGetSymbolAddress((void**)&ah, g_ah);

    cudaFuncSetAttribute(mma_gemm4, cudaFuncAttributeMaxDynamicSharedMemorySize, SMEM_DYN);

    conv_all<<<(XN4 + 4 * WN4) / 256, 256>>>(x, Wq, Wk, Wv, Wo);

    // Fused Q/K/V projections (fp16 out, head layout); Q,K get the feature map.
    mma_gemm4<<<dim3(DD / BN, MM / BM, 3), 256, SMEM_DYN>>>(
        xh, wh, bq, bk, bv, nullptr, q, k, v, 1, 1, 0, /*head_layout=*/1);

    chunk_kv_mma<<<dim3(NC, BH), 128>>>();
    prefix_scan<<<dim3(8, BH), 256>>>();
    attn_mma<<<dim3(NC, BH), 128>>>();

    // Output projection (fp32 out)
    mma_gemm4<<<dim3(DD / BN, MM / BM, 1), 256, SMEM_DYN>>>(
        ah, wh + 3 * (size_t)DD * DD, bo, bo, bo, out, nullptr, nullptr, nullptr,
        0, 0, 0, /*head_layout=*/0);
}

// round 16
// speedup vs baseline: 1.0234x; 1.0005x over previous
#include <cuda_runtime.h>
#include <cuda_fp16.h>
#include <cstdint>

// Problem constants
#define BB   2
#define TT   2048
#define DD   1024
#define HH   16
#define DH   64
#define NC   32           // TT / 64 chunks
#define BH   32           // BB * HH
#define MM   4096         // BB * TT
#define EPSF 1e-6f

// GEMM tiling (round-10 proven config: BK=32, 3-stage cp.async, 2 CTAs/SM)
#define BM   128
#define BN   128
#define BK   32
#define NKB  (DD / BK)    // 32 k-stages
#define ROWB  80          // padded row stride bytes (32 fp16 + 16B pad)
#define TILEB (128 * ROWB)
#define STG   (2 * TILEB)
#define NSTG  3
#define SMEM_DYN (NSTG * STG)       // 61440 B

#define XN4 (MM * DD / 4)
#define WN4 (DD * DD / 4)

// attention smem row stride: 72 fp16 = 144B (conflict-free LDSM)
#define SR 72

// Scratch (device globals; allocation is forbidden)
__device__ __half g_q[BH * TT * DH];        // [b,h,t,dh] fp16
__device__ __half g_k[BH * TT * DH];
__device__ __half g_v[BH * TT * DH];
__device__ __half g_kvh[BH * NC * DH * DH]; // per-chunk KV (fp16)
__device__ __half g_sh[BH * NC * DH * DH];  // exclusive-prefix S (fp16)
__device__ float  g_ks[BH * NC * DH];       // k-sum, then exclusive prefix (fp32)

// Persistent fp16 copies
__device__ __half g_xh[MM * DD];
__device__ __half g_wh[4 * DD * DD];        // Wq | Wk | Wv | Wo
__device__ __half g_ah[MM * DD];            // attention output

// ---------------------------------------------------------------------------
// helpers
// ---------------------------------------------------------------------------
__device__ __forceinline__ uint32_t smem_u32(const void* p) {
    uint32_t a;
    asm("{ .reg .u64 t; cvta.to.shared.u64 t, %1; cvt.u32.u64 %0, t; }"
        : "=r"(a) : "l"(p));
    return a;
}
__device__ __forceinline__ uint32_t packf2h(float lo, float hi) {
    __half2 h = __floats2half2_rn(lo, hi);
    return *(uint32_t*)&h;
}
__device__ __forceinline__ void mma16816(float* c, const uint32_t* a, const uint32_t* b) {
    asm volatile(
        "mma.sync.aligned.m16n8k16.row.col.f32.f16.f16.f32 "
        "{%0,%1,%2,%3}, {%4,%5,%6,%7}, {%8,%9}, {%0,%1,%2,%3};"
        : "+f"(c[0]), "+f"(c[1]), "+f"(c[2]), "+f"(c[3])
        : "r"(a[0]), "r"(a[1]), "r"(a[2]), "r"(a[3]), "r"(b[0]), "r"(b[1]));
}
__device__ __forceinline__ void ldsm4(uint32_t* r, uint32_t addr) {
    asm volatile("ldmatrix.sync.aligned.m8n8.x4.shared.b16 {%0,%1,%2,%3}, [%4];"
                 : "=r"(r[0]), "=r"(r[1]), "=r"(r[2]), "=r"(r[3]) : "r"(addr));
}
__device__ __forceinline__ void ldsm4t(uint32_t* r, uint32_t addr) {
    asm volatile("ldmatrix.sync.aligned.m8n8.x4.trans.shared.b16 {%0,%1,%2,%3}, [%4];"
                 : "=r"(r[0]), "=r"(r[1]), "=r"(r[2]), "=r"(r[3]) : "r"(addr));
}
__device__ __forceinline__ void cp16(uint32_t dst, const void* src) {
    asm volatile("cp.async.cg.shared.global [%0], [%1], 16;"
                 :: "r"(dst), "l"(src) : "memory");
}
#define CP_COMMIT() asm volatile("cp.async.commit_group;" ::: "memory")
#define CP_WAIT1()  asm volatile("cp.async.wait_group 1;"  ::: "memory")
#define CP_WAIT0()  asm volatile("cp.async.wait_group 0;"  ::: "memory")

// ---------------------------------------------------------------------------
// Fused one-time fp32 -> fp16 cast: x then Wq/Wk/Wv/Wo  (round-10 config)
// ---------------------------------------------------------------------------
__global__ __launch_bounds__(256) void conv_all(
    const float* __restrict__ x,
    const float* __restrict__ Wq, const float* __restrict__ Wk,
    const float* __restrict__ Wv, const float* __restrict__ Wo)
{
    const int i = blockIdx.x * 256 + threadIdx.x;
    const float* src;
    __half* dst;
    int j;
    if (i < XN4) {
        src = x; dst = g_xh; j = i;
    } else {
        const int t = i - XN4;
        const int w = t / WN4;
        j = t - w * WN4;
        src = (w == 0) ? Wq : (w == 1) ? Wk : (w == 2) ? Wv : Wo;
        dst = g_wh + (size_t)w * DD * DD;
    }
    float4 v = ((const float4*)src)[j];
    uint2 u;
    u.x = packf2h(v.x, v.y);
    u.y = packf2h(v.z, v.w);
    ((uint2*)dst)[j] = u;
}

// ---------------------------------------------------------------------------
// fp16 tensor-core GEMM. head_layout: write fp16 to h0/h1/h2 in [b,h,t,dh];
// else write fp32 to o0 in [m][n]. BK=32, 2 CTAs/SM, cp.async 3-stage, ldmatrix.
// ---------------------------------------------------------------------------
__global__ __launch_bounds__(256, 2) void mma_gemm4(
    const __half* __restrict__ A, const __half* __restrict__ W,
    const float* __restrict__ bz0, const float* __restrict__ bz1, const float* __restrict__ bz2,
    float* __restrict__ o0,
    __half* __restrict__ h0, __half* __restrict__ h1, __half* __restrict__ h2,
    int f0, int f1, int f2, int head_layout)
{
    extern __shared__ char dsm[];

    const int z = blockIdx.z;
    const __half* B = W + (size_t)z * DD * DD;
    const float* bias = (z == 0) ? bz0 : (z == 1) ? bz1 : bz2;
    __half*      houtp = (z == 0) ? h0 : (z == 1) ? h1 : h2;
    const int    fm   = (z == 0) ? f0  : (z == 1) ? f1  : f2;

    const int tid  = threadIdx.x;
    const int wid  = tid >> 5, lane = tid & 31;
    const int m0   = blockIdx.y * BM, n0 = blockIdx.x * BN;
    const int wm   = (wid >> 2) * 64, wn = (wid & 3) * 32;
    const int g    = lane >> 2, tig = lane & 3;
    const uint32_t sb = smem_u32(dsm);

    float acc[4][4][4];
    #pragma unroll
    for (int i = 0; i < 4; i++)
        #pragma unroll
        for (int j = 0; j < 4; j++)
            #pragma unroll
            for (int q = 0; q < 4; q++) acc[i][j][q] = 0.f;

    const int srow = tid >> 1;
    const int scol = (tid & 1) * 16;
    const uint32_t doff = (uint32_t)srow * ROWB + scol * 2;

    auto issue = [&](int c, int s) {
        const uint32_t base = sb + s * STG;
        const int kb = c * BK;
        const __half* ap = A + (size_t)(m0 + srow) * DD + kb + scol;
        const __half* bp = B + (size_t)(n0 + srow) * DD + kb + scol;
        cp16(base + doff,              ap);
        cp16(base + doff + 16,         ap + 8);
        cp16(base + TILEB + doff,      bp);
        cp16(base + TILEB + doff + 16, bp + 8);
    };

    auto compute = [&](int s) {
        const uint32_t base = sb + s * STG;
        #pragma unroll
        for (int kt = 0; kt < 2; kt++) {
            const uint32_t kby = kt * 32;
            uint32_t bf[4][2];
            #pragma unroll
            for (int ntp = 0; ntp < 2; ntp++) {
                const uint32_t baddr = base + TILEB +
                    (uint32_t)(wn + ntp * 16 + ((lane >> 4) & 1) * 8 + (lane & 7)) * ROWB +
                    kby + ((lane >> 3) & 1) * 16;
                uint32_t t[4];
                ldsm4(t, baddr);
                bf[2 * ntp][0] = t[0];     bf[2 * ntp][1] = t[1];
                bf[2 * ntp + 1][0] = t[2]; bf[2 * ntp + 1][1] = t[3];
            }
            #pragma unroll
            for (int mt = 0; mt < 4; mt++) {
                const uint32_t aaddr = base +
                    (uint32_t)(wm + mt * 16 + ((lane >> 3) & 1) * 8 + (lane & 7)) * ROWB +
                    kby + ((lane >> 4) & 1) * 16;
                uint32_t af[4];
                ldsm4(af, aaddr);
                #pragma unroll
                for (int nt = 0; nt < 4; nt++)
                    mma16816(acc[mt][nt], af, bf[nt]);
            }
        }
    };

    issue(0, 0); CP_COMMIT();
    issue(1, 1); CP_COMMIT();

    for (int c = 0; c < NKB; c++) {
        CP_WAIT1();
        __syncthreads();
        compute(c % NSTG);
        if (c + 2 < NKB) issue(c + 2, (c + 2) % NSTG);
        CP_COMMIT();
    }

    const int hcol = (n0 + wn) >> 6;
    #pragma unroll
    for (int mt = 0; mt < 4; mt++) {
        const int r0 = m0 + wm + mt * 16 + g;
        #pragma unroll
        for (int nt = 0; nt < 4; nt++) {
            const int cn = n0 + wn + nt * 8 + 2 * tig;
            float v0 = acc[mt][nt][0] + bias[cn];
            float v1 = acc[mt][nt][1] + bias[cn + 1];
            float v2 = acc[mt][nt][2] + bias[cn];
            float v3 = acc[mt][nt][3] + bias[cn + 1];
            if (fm) {
                v0 = (v0 > 0.f) ? (v0 + 1.f) : expf(v0);
                v1 = (v1 > 0.f) ? (v1 + 1.f) : expf(v1);
                v2 = (v2 > 0.f) ? (v2 + 1.f) : expf(v2);
                v3 = (v3 > 0.f) ? (v3 + 1.f) : expf(v3);
            }
            if (head_layout) {
                const int b = r0 >> 11, t = r0 & (TT - 1);
                const int dh = cn & 63;
                __half* p = houtp + ((size_t)((b * HH + hcol) * TT + t)) * DH + dh;
                *(uint32_t*)p            = packf2h(v0, v1);
                *(uint32_t*)(p + 8 * DH) = packf2h(v2, v3);
            } else {
                float* p = o0 + (size_t)r0 * DD + cn;
                *(float2*)p            = make_float2(v0, v1);
                *(float2*)(p + 8 * DD) = make_float2(v2, v3);
            }
        }
    }
}

// ---------------------------------------------------------------------------
// chunk_kv via mma: KV[d][e] = sum_t K[t][d] V[t][e]  -> fp16 out
// ---------------------------------------------------------------------------
__global__ __launch_bounds__(128) void chunk_kv_mma()
{
    __shared__ __half Ks[64 * SR];
    __shared__ __half Vs[64 * SR];

    const int c = blockIdx.x, bh = blockIdx.y;
    const int tid = threadIdx.x;
    const int wid = tid >> 5, lane = tid & 31;
    const int g = lane >> 2, tig = lane & 3;
    const int wm = wid * 16;

    const __half* kp = g_k + ((size_t)bh * TT + c * 64) * DH;
    const __half* vp = g_v + ((size_t)bh * TT + c * 64) * DH;
    const int lr = tid >> 1, lc = (tid & 1) * 32;
    #pragma unroll
    for (int u = 0; u < 4; u++) {
        *(uint4*)(Ks + lr * SR + lc + u * 8) = *(const uint4*)(kp + lr * 64 + lc + u * 8);
        *(uint4*)(Vs + lr * SR + lc + u * 8) = *(const uint4*)(vp + lr * 64 + lc + u * 8);
    }
    __syncthreads();

    const uint32_t kb = smem_u32(Ks), vb = smem_u32(Vs);
    float acc[8][4];
    #pragma unroll
    for (int i = 0; i < 8; i++)
        #pragma unroll
        for (int q = 0; q < 4; q++) acc[i][q] = 0.f;

    #pragma unroll
    for (int ks = 0; ks < 4; ks++) {
        const int t0 = ks * 16;
        uint32_t ka[4];
        ldsm4t(ka, kb + (uint32_t)(t0 + ((lane >> 4) & 1) * 8 + (lane & 7)) * (SR * 2)
                     + wm * 2 + ((lane >> 3) & 1) * 16);
        #pragma unroll
        for (int ntp = 0; ntp < 4; ntp++) {
            uint32_t t[4];
            ldsm4t(t, vb + (uint32_t)(t0 + ((lane >> 3) & 1) * 8 + (lane & 7)) * (SR * 2)
                        + ntp * 32 + ((lane >> 4) & 1) * 16);
            uint32_t b0[2] = { t[0], t[1] }, b1[2] = { t[2], t[3] };
            mma16816(acc[2 * ntp],     ka, b0);
            mma16816(acc[2 * ntp + 1], ka, b1);
        }
    }

    __half* kvout = g_kvh + ((size_t)bh * NC + c) * 4096;
    #pragma unroll
    for (int nt = 0; nt < 8; nt++) {
        const int col = nt * 8 + 2 * tig;
        *(uint32_t*)(kvout + (wm + g) * 64 + col)     = packf2h(acc[nt][0], acc[nt][1]);
        *(uint32_t*)(kvout + (wm + g + 8) * 64 + col) = packf2h(acc[nt][2], acc[nt][3]);
    }

    if (tid < 64) {
        float s = 0.f;
        #pragma unroll 8
        for (int t = 0; t < 64; t++) s += __half2float(Ks[t * SR + tid]);
        g_ks[((size_t)bh * NC + c) * 64 + tid] = s;
    }
}

// ---------------------------------------------------------------------------
// Exclusive prefix scan across chunks; fp16 in (g_kvh), fp16 out (g_sh).
// 2 adjacent positions per thread (__half2); register-prefetched (MLP=32).
// grid (8, BH) x 256 threads.  (round-10 proven config)
// ---------------------------------------------------------------------------
__global__ __launch_bounds__(256) void prefix_scan()
{
    const int bh = blockIdx.y;
    const int p2 = blockIdx.x * 256 + threadIdx.x;   // 0..2047 (pairs)
    const __half* base = g_kvh + (size_t)bh * NC * 4096 + p2 * 2;
    __half* outp = g_sh + (size_t)bh * NC * 4096 + p2 * 2;

    __half2 v[NC];
    #pragma unroll
    for (int c = 0; c < NC; c++) v[c] = *(const __half2*)(base + c * 4096);
    float2 run = make_float2(0.f, 0.f);
    #pragma unroll
    for (int c = 0; c < NC; c++) {
        *(__half2*)(outp + c * 4096) = __floats2half2_rn(run.x, run.y);
        float2 f = __half22float2(v[c]);
        run.x += f.x; run.y += f.y;
    }

    if (blockIdx.x == 0 && threadIdx.x < 64) {
        float w[NC];
        float* kbp = g_ks + (size_t)bh * NC * 64 + threadIdx.x;
        #pragma unroll
        for (int c = 0; c < NC; c++) w[c] = kbp[c * 64];
        float r2 = 0.f;
        #pragma unroll
        for (int c = 0; c < NC; c++) {
            kbp[c * 64] = r2;
            r2 += w[c];
        }
    }
}

// ---------------------------------------------------------------------------
// Attention chunk via mma: A = mask(QK^T); out = (A V + Q S) / (rowsum(A)+Qz)
// Q/K load synchronously; V/S prefetch via cp.async overlapped with GEMM1.
// Writes fp16 g_ah for the O-gemm.
// ---------------------------------------------------------------------------
__global__ __launch_bounds__(128) void attn_mma()
{
    __shared__ __half Qs[64 * SR];
    __shared__ __half Ks[64 * SR];   // K, then reused as A
    __shared__ __half Vs[64 * SR];
    __shared__ __half Ss[64 * SR];
    __shared__ float  zs[64];

    const int c = blockIdx.x, bh = blockIdx.y;
    const int tid = threadIdx.x;
    const int wid = tid >> 5, lane = tid & 31;
    const int g = lane >> 2, tig = lane & 3;
    const int wm = wid * 16;

    const __half* qp = g_q + ((size_t)bh * TT + c * 64) * DH;
    const __half* kp = g_k + ((size_t)bh * TT + c * 64) * DH;
    const __half* vp = g_v + ((size_t)bh * TT + c * 64) * DH;
    const __half* sp = g_sh + ((size_t)bh * NC + c) * 4096;

    const int lr = tid >> 1, lc = (tid & 1) * 32;
    const uint32_t vsm = smem_u32(Vs), ssm = smem_u32(Ss);
    // async prefetch of V and S (first used after the A-write barrier)
    #pragma unroll
    for (int u = 0; u < 2; u++) {
        const uint32_t so = (uint32_t)lr * (SR * 2) + (lc + u * 16) * 2;
        cp16(vsm + so,      vp + lr * 64 + lc + u * 16);
        cp16(vsm + so + 16, vp + lr * 64 + lc + u * 16 + 8);
        cp16(ssm + so,      sp + lr * 64 + lc + u * 16);
        cp16(ssm + so + 16, sp + lr * 64 + lc + u * 16 + 8);
    }
    CP_COMMIT();
    // synchronous Q/K loads (needed for GEMM1 immediately)
    #pragma unroll
    for (int u = 0; u < 4; u++) {
        *(uint4*)(Qs + lr * SR + lc + u * 8) = *(const uint4*)(qp + lr * 64 + lc + u * 8);
        *(uint4*)(Ks + lr * SR + lc + u * 8) = *(const uint4*)(kp + lr * 64 + lc + u * 8);
    }
    if (tid < 64) zs[tid] = g_ks[((size_t)bh * NC + c) * 64 + tid];
    __syncthreads();

    const uint32_t qb = smem_u32(Qs), kb = smem_u32(Ks);
    const uint32_t vb = vsm, sb = ssm;

    // ---- GEMM1: A = Q K^T ----
    float aa[8][4];
    #pragma unroll
    for (int i = 0; i < 8; i++)
        #pragma unroll
        for (int q = 0; q < 4; q++) aa[i][q] = 0.f;

    #pragma unroll
    for (int ks = 0; ks < 4; ks++) {
        const uint32_t kby = ks * 32;
        uint32_t qa[4];
        ldsm4(qa, qb + (uint32_t)(wm + ((lane >> 3) & 1) * 8 + (lane & 7)) * (SR * 2)
                    + kby + ((lane >> 4) & 1) * 16);
        #pragma unroll
        for (int ntp = 0; ntp < 4; ntp++) {
            uint32_t t[4];
            ldsm4(t, kb + (uint32_t)(ntp * 16 + ((lane >> 4) & 1) * 8 + (lane & 7)) * (SR * 2)
                       + kby + ((lane >> 3) & 1) * 16);
            uint32_t b0[2] = { t[0], t[1] }, b1[2] = { t[2], t[3] };
            mma16816(aa[2 * ntp],     qa, b0);
            mma16816(aa[2 * ntp + 1], qa, b1);
        }
    }

    // mask + rowsum
    const int r0 = wm + g, r1 = r0 + 8;
    float rs0 = 0.f, rs1 = 0.f;
    #pragma unroll
    for (int nt = 0; nt < 8; nt++) {
        const int c0 = nt * 8 + 2 * tig, c1 = c0 + 1;
        if (c0 > r0) aa[nt][0] = 0.f;
        if (c1 > r0) aa[nt][1] = 0.f;
        if (c0 > r1) aa[nt][2] = 0.f;
        if (c1 > r1) aa[nt][3] = 0.f;
        rs0 += aa[nt][0] + aa[nt][1];
        rs1 += aa[nt][2] + aa[nt][3];
    }
    #pragma unroll
    for (int off = 1; off < 4; off <<= 1) {
        rs0 += __shfl_xor_sync(0xffffffffu, rs0, off);
        rs1 += __shfl_xor_sync(0xffffffffu, rs1, off);
    }

    // qz
    float qz0 = 0.f, qz1 = 0.f;
    #pragma unroll 8
    for (int d2 = 0; d2 < 32; d2++) {
        float2 z2 = *(const float2*)(zs + 2 * d2);
        float2 q0 = __half22float2(*(const __half2*)(Qs + r0 * SR + 2 * d2));
        float2 q1 = __half22float2(*(const __half2*)(Qs + r1 * SR + 2 * d2));
        qz0 += q0.x * z2.x + q0.y * z2.y;
        qz1 += q1.x * z2.x + q1.y * z2.y;
    }

    // write masked A (fp16) into Ks
    __syncthreads();
    #pragma unroll
    for (int nt = 0; nt < 8; nt++) {
        const int col = nt * 8 + 2 * tig;
        *(uint32_t*)(Ks + r0 * SR + col) = packf2h(aa[nt][0], aa[nt][1]);
        *(uint32_t*)(Ks + r1 * SR + col) = packf2h(aa[nt][2], aa[nt][3]);
    }
    CP_WAIT0();          // V/S prefetch complete (per-thread)
    __syncthreads();     // publish A + V/S to all threads

    // ---- GEMM2: out = A V + GEMM3: out += Q S ----
    float oc[8][4];
    #pragma unroll
    for (int i = 0; i < 8; i++)
        #pragma unroll
        for (int q = 0; q < 4; q++) oc[i][q] = 0.f;

    #pragma unroll
    for (int ks = 0; ks < 4; ks++) {
        const uint32_t kby = ks * 32;
        uint32_t af[4];
        ldsm4(af, kb + (uint32_t)(wm + ((lane >> 3) & 1) * 8 + (lane & 7)) * (SR * 2)
                    + kby + ((lane >> 4) & 1) * 16);
        #pragma unroll
        for (int ntp = 0; ntp < 4; ntp++) {
            uint32_t t[4];
            ldsm4t(t, vb + (uint32_t)(ks * 16 + ((lane >> 3) & 1) * 8 + (lane & 7)) * (SR * 2)
                        + ntp * 32 + ((lane >> 4) & 1) * 16);
            uint32_t b0[2] = { t[0], t[1] }, b1[2] = { t[2], t[3] };
            mma16816(oc[2 * ntp],     af, b0);
            mma16816(oc[2 * ntp + 1], af, b1);
        }
    }
    #pragma unroll
    for (int ks = 0; ks < 4; ks++) {
        const uint32_t kby = ks * 32;
        uint32_t qa[4];
        ldsm4(qa, qb + (uint32_t)(wm + ((lane >> 3) & 1) * 8 + (lane & 7)) * (SR * 2)
                    + kby + ((lane >> 4) & 1) * 16);
        #pragma unroll
        for (int ntp = 0; ntp < 4; ntp++) {
            uint32_t t[4];
            ldsm4t(t, sb + (uint32_t)(ks * 16 + ((lane >> 3) & 1) * 8 + (lane & 7)) * (SR * 2)
                        + ntp * 32 + ((lane >> 4) & 1) * 16);
            uint32_t b0[2] = { t[0], t[1] }, b1[2] = { t[2], t[3] };
            mma16816(oc[2 * ntp],     qa, b0);
            mma16816(oc[2 * ntp + 1], qa, b1);
        }
    }

    const float inv0 = 1.f / fmaxf(rs0 + qz0, EPSF);
    const float inv1 = 1.f / fmaxf(rs1 + qz1, EPSF);
    const int b = bh >> 4, h = bh & 15;
    __half* p0 = g_ah + ((size_t)(b * TT + c * 64 + r0)) * DD + h * 64;
    __half* p1 = g_ah + ((size_t)(b * TT + c * 64 + r1)) * DD + h * 64;
    #pragma unroll
    for (int nt = 0; nt < 8; nt++) {
        const int col = nt * 8 + 2 * tig;
        *(uint32_t*)(p0 + col) = packf2h(oc[nt][0] * inv0, oc[nt][1] * inv0);
        *(uint32_t*)(p1 + col) = packf2h(oc[nt][2] * inv1, oc[nt][3] * inv1);
    }
}

// ---------------------------------------------------------------------------
extern "C" void kernel_launch(void* const* d_in, const int* in_sizes, int n_in,
                              void* d_out, int out_size)
{
    const float* x  = (const float*)d_in[0];
    const float* Wq = (const float*)d_in[1];
    const float* bq = (const float*)d_in[2];
    const float* Wk = (const float*)d_in[3];
    const float* bk = (const float*)d_in[4];
    const float* Wv = (const float*)d_in[5];
    const float* bv = (const float*)d_in[6];
    const float* Wo = (const float*)d_in[7];
    const float* bo = (const float*)d_in[8];
    float* out = (float*)d_out;

    __half *q, *k, *v, *xh, *wh, *ah;
    cudaGetSymbolAddress((void**)&q,  g_q);
    cudaGetSymbolAddress((void**)&k,  g_k);
    cudaGetSymbolAddress((void**)&v,  g_v);
    cudaGetSymbolAddress((void**)&xh, g_xh);
    cudaGetSymbolAddress((void**)&wh, g_wh);
    cudaGetSymbolAddress((void**)&ah, g_ah);

    cudaFuncSetAttribute(mma_gemm4, cudaFuncAttributeMaxDynamicSharedMemorySize, SMEM_DYN);

    conv_all<<<(XN4 + 4 * WN4) / 256, 256>>>(x, Wq, Wk, Wv, Wo);

    // Fused Q/K/V projections (fp16 out, head layout); Q,K get the feature map.
    mma_gemm4<<<dim3(DD / BN, MM / BM, 3), 256, SMEM_DYN>>>(
        xh, wh, bq, bk, bv, nullptr, q, k, v, 1, 1, 0, /*head_layout=*/1);

    chunk_kv_mma<<<dim3(NC, BH), 128>>>();
    prefix_scan<<<dim3(8, BH), 256>>>();
    attn_mma<<<dim3(NC, BH), 128>>>();

    // Output projection (fp32 out)
    mma_gemm4<<<dim3(DD / BN, MM / BM, 1), 256, SMEM_DYN>>>(
        ah, wh + 3 * (size_t)DD * DD, bo, bo, bo, out, nullptr, nullptr, nullptr,
        0, 0, 0, /*head_layout=*/0);
}

// round 17
// speedup vs baseline: 1.0349x; 1.0112x over previous
#include <cuda_runtime.h>
#include <cuda_fp16.h>
#include <cstdint>

// Problem constants
#define BB   2
#define TT   2048
#define DD   1024
#define HH   16
#define DH   64
#define NC   32           // TT / 64 chunks
#define BH   32           // BB * HH
#define MM   4096         // BB * TT
#define EPSF 1e-6f

// GEMM tiling (proven config: BK=32, 3-stage cp.async, 2 CTAs/SM)
#define BM   128
#define BN   128
#define BK   32
#define NKB  (DD / BK)    // 32 k-stages
#define ROWB  80          // padded row stride bytes (32 fp16 + 16B pad)
#define TILEB (128 * ROWB)
#define STG   (2 * TILEB)
#define NSTG  3
#define SMEM_DYN (NSTG * STG)       // 61440 B

#define XN4 (MM * DD / 4)
#define WN4 (DD * DD / 4)
#define CN4 (XN4 + 4 * WN4)

// attention smem row stride: 72 fp16 = 144B (conflict-free LDSM)
#define SR 72

// Scratch (device globals; allocation is forbidden)
__device__ __half g_q[BH * TT * DH];        // [b,h,t,dh] fp16
__device__ __half g_k[BH * TT * DH];
__device__ __half g_v[BH * TT * DH];
__device__ __half g_kvh[BH * NC * DH * DH]; // per-chunk KV (fp16)
__device__ __half g_sh[BH * NC * DH * DH];  // exclusive-prefix S (fp16)
__device__ float  g_ks[BH * NC * DH];       // k-sum, then exclusive prefix (fp32)

// Persistent fp16 copies
__device__ __half g_xh[MM * DD];
__device__ __half g_wh[4 * DD * DD];        // Wq | Wk | Wv | Wo
__device__ __half g_ah[MM * DD];            // attention output

// ---------------------------------------------------------------------------
// helpers
// ---------------------------------------------------------------------------
__device__ __forceinline__ uint32_t smem_u32(const void* p) {
    uint32_t a;
    asm("{ .reg .u64 t; cvta.to.shared.u64 t, %1; cvt.u32.u64 %0, t; }"
        : "=r"(a) : "l"(p));
    return a;
}
__device__ __forceinline__ uint32_t packf2h(float lo, float hi) {
    __half2 h = __floats2half2_rn(lo, hi);
    return *(uint32_t*)&h;
}
__device__ __forceinline__ void mma16816(float* c, const uint32_t* a, const uint32_t* b) {
    asm volatile(
        "mma.sync.aligned.m16n8k16.row.col.f32.f16.f16.f32 "
        "{%0,%1,%2,%3}, {%4,%5,%6,%7}, {%8,%9}, {%0,%1,%2,%3};"
        : "+f"(c[0]), "+f"(c[1]), "+f"(c[2]), "+f"(c[3])
        : "r"(a[0]), "r"(a[1]), "r"(a[2]), "r"(a[3]), "r"(b[0]), "r"(b[1]));
}
__device__ __forceinline__ void ldsm4(uint32_t* r, uint32_t addr) {
    asm volatile("ldmatrix.sync.aligned.m8n8.x4.shared.b16 {%0,%1,%2,%3}, [%4];"
                 : "=r"(r[0]), "=r"(r[1]), "=r"(r[2]), "=r"(r[3]) : "r"(addr));
}
__device__ __forceinline__ void ldsm4t(uint32_t* r, uint32_t addr) {
    asm volatile("ldmatrix.sync.aligned.m8n8.x4.trans.shared.b16 {%0,%1,%2,%3}, [%4];"
                 : "=r"(r[0]), "=r"(r[1]), "=r"(r[2]), "=r"(r[3]) : "r"(addr));
}
__device__ __forceinline__ void cp16(uint32_t dst, const void* src) {
    asm volatile("cp.async.cg.shared.global [%0], [%1], 16;"
                 :: "r"(dst), "l"(src) : "memory");
}
#define CP_COMMIT() asm volatile("cp.async.commit_group;" ::: "memory")
#define CP_WAIT1()  asm volatile("cp.async.wait_group 1;"  ::: "memory")
#define CP_WAIT0()  asm volatile("cp.async.wait_group 0;"  ::: "memory")

// ---------------------------------------------------------------------------
// Fused one-time fp32 -> fp16 cast: x then Wq/Wk/Wv/Wo.
// Fixed 4 float4/thread (MLP=4, loads issued back-to-back). Each CTA's
// 1024-float4 block lies entirely within one source tensor (XN4, WN4 are
// multiples of 1024), so the region classification is done once per thread.
// ---------------------------------------------------------------------------
__global__ __launch_bounds__(256) void conv_all(
    const float* __restrict__ x,
    const float* __restrict__ Wq, const float* __restrict__ Wk,
    const float* __restrict__ Wv, const float* __restrict__ Wo)
{
    const int i0 = blockIdx.x * 1024 + threadIdx.x;   // first of 4 items
    const float* src;
    __half* dst;
    int j0;
    if (i0 < XN4) {
        src = x; dst = g_xh; j0 = i0;
    } else {
        const int t = i0 - XN4;
        const int w = t / WN4;
        j0 = t - w * WN4;
        src = (w == 0) ? Wq : (w == 1) ? Wk : (w == 2) ? Wv : Wo;
        dst = g_wh + (size_t)w * DD * DD;
    }
    float4 v0 = ((const float4*)src)[j0];
    float4 v1 = ((const float4*)src)[j0 + 256];
    float4 v2 = ((const float4*)src)[j0 + 512];
    float4 v3 = ((const float4*)src)[j0 + 768];
    uint2 u;
    u.x = packf2h(v0.x, v0.y); u.y = packf2h(v0.z, v0.w);
    ((uint2*)dst)[j0] = u;
    u.x = packf2h(v1.x, v1.y); u.y = packf2h(v1.z, v1.w);
    ((uint2*)dst)[j0 + 256] = u;
    u.x = packf2h(v2.x, v2.y); u.y = packf2h(v2.z, v2.w);
    ((uint2*)dst)[j0 + 512] = u;
    u.x = packf2h(v3.x, v3.y); u.y = packf2h(v3.z, v3.w);
    ((uint2*)dst)[j0 + 768] = u;
}

// ---------------------------------------------------------------------------
// fp16 tensor-core GEMM. head_layout: write fp16 to h0/h1/h2 in [b,h,t,dh];
// else write fp32 to o0 in [m][n]. BK=32, 2 CTAs/SM, cp.async 3-stage, ldmatrix.
// ---------------------------------------------------------------------------
__global__ __launch_bounds__(256, 2) void mma_gemm4(
    const __half* __restrict__ A, const __half* __restrict__ W,
    const float* __restrict__ bz0, const float* __restrict__ bz1, const float* __restrict__ bz2,
    float* __restrict__ o0,
    __half* __restrict__ h0, __half* __restrict__ h1, __half* __restrict__ h2,
    int f0, int f1, int f2, int head_layout)
{
    extern __shared__ char dsm[];

    const int z = blockIdx.z;
    const __half* B = W + (size_t)z * DD * DD;
    const float* bias = (z == 0) ? bz0 : (z == 1) ? bz1 : bz2;
    __half*      houtp = (z == 0) ? h0 : (z == 1) ? h1 : h2;
    const int    fm   = (z == 0) ? f0  : (z == 1) ? f1  : f2;

    const int tid  = threadIdx.x;
    const int wid  = tid >> 5, lane = tid & 31;
    const int m0   = blockIdx.y * BM, n0 = blockIdx.x * BN;
    const int wm   = (wid >> 2) * 64, wn = (wid & 3) * 32;
    const int g    = lane >> 2, tig = lane & 3;
    const uint32_t sb = smem_u32(dsm);

    float acc[4][4][4];
    #pragma unroll
    for (int i = 0; i < 4; i++)
        #pragma unroll
        for (int j = 0; j < 4; j++)
            #pragma unroll
            for (int q = 0; q < 4; q++) acc[i][j][q] = 0.f;

    const int srow = tid >> 1;
    const int scol = (tid & 1) * 16;
    const uint32_t doff = (uint32_t)srow * ROWB + scol * 2;

    auto issue = [&](int c, int s) {
        const uint32_t base = sb + s * STG;
        const int kb = c * BK;
        const __half* ap = A + (size_t)(m0 + srow) * DD + kb + scol;
        const __half* bp = B + (size_t)(n0 + srow) * DD + kb + scol;
        cp16(base + doff,              ap);
        cp16(base + doff + 16,         ap + 8);
        cp16(base + TILEB + doff,      bp);
        cp16(base + TILEB + doff + 16, bp + 8);
    };

    auto compute = [&](int s) {
        const uint32_t base = sb + s * STG;
        #pragma unroll
        for (int kt = 0; kt < 2; kt++) {
            const uint32_t kby = kt * 32;
            uint32_t bf[4][2];
            #pragma unroll
            for (int ntp = 0; ntp < 2; ntp++) {
                const uint32_t baddr = base + TILEB +
                    (uint32_t)(wn + ntp * 16 + ((lane >> 4) & 1) * 8 + (lane & 7)) * ROWB +
                    kby + ((lane >> 3) & 1) * 16;
                uint32_t t[4];
                ldsm4(t, baddr);
                bf[2 * ntp][0] = t[0];     bf[2 * ntp][1] = t[1];
                bf[2 * ntp + 1][0] = t[2]; bf[2 * ntp + 1][1] = t[3];
            }
            #pragma unroll
            for (int mt = 0; mt < 4; mt++) {
                const uint32_t aaddr = base +
                    (uint32_t)(wm + mt * 16 + ((lane >> 3) & 1) * 8 + (lane & 7)) * ROWB +
                    kby + ((lane >> 4) & 1) * 16;
                uint32_t af[4];
                ldsm4(af, aaddr);
                #pragma unroll
                for (int nt = 0; nt < 4; nt++)
                    mma16816(acc[mt][nt], af, bf[nt]);
            }
        }
    };

    issue(0, 0); CP_COMMIT();
    issue(1, 1); CP_COMMIT();

    for (int c = 0; c < NKB; c++) {
        CP_WAIT1();
        __syncthreads();
        compute(c % NSTG);
        if (c + 2 < NKB) issue(c + 2, (c + 2) % NSTG);
        CP_COMMIT();
    }

    const int hcol = (n0 + wn) >> 6;
    #pragma unroll
    for (int mt = 0; mt < 4; mt++) {
        const int r0 = m0 + wm + mt * 16 + g;
        #pragma unroll
        for (int nt = 0; nt < 4; nt++) {
            const int cn = n0 + wn + nt * 8 + 2 * tig;
            float v0 = acc[mt][nt][0] + bias[cn];
            float v1 = acc[mt][nt][1] + bias[cn + 1];
            float v2 = acc[mt][nt][2] + bias[cn];
            float v3 = acc[mt][nt][3] + bias[cn + 1];
            if (fm) {
                v0 = (v0 > 0.f) ? (v0 + 1.f) : expf(v0);
                v1 = (v1 > 0.f) ? (v1 + 1.f) : expf(v1);
                v2 = (v2 > 0.f) ? (v2 + 1.f) : expf(v2);
                v3 = (v3 > 0.f) ? (v3 + 1.f) : expf(v3);
            }
            if (head_layout) {
                const int b = r0 >> 11, t = r0 & (TT - 1);
                const int dh = cn & 63;
                __half* p = houtp + ((size_t)((b * HH + hcol) * TT + t)) * DH + dh;
                *(uint32_t*)p            = packf2h(v0, v1);
                *(uint32_t*)(p + 8 * DH) = packf2h(v2, v3);
            } else {
                float* p = o0 + (size_t)r0 * DD + cn;
                *(float2*)p            = make_float2(v0, v1);
                *(float2*)(p + 8 * DD) = make_float2(v2, v3);
            }
        }
    }
}

// ---------------------------------------------------------------------------
// chunk_kv via mma: KV[d][e] = sum_t K[t][d] V[t][e]  -> fp16 out
// ---------------------------------------------------------------------------
__global__ __launch_bounds__(128) void chunk_kv_mma()
{
    __shared__ __half Ks[64 * SR];
    __shared__ __half Vs[64 * SR];

    const int c = blockIdx.x, bh = blockIdx.y;
    const int tid = threadIdx.x;
    const int wid = tid >> 5, lane = tid & 31;
    const int g = lane >> 2, tig = lane & 3;
    const int wm = wid * 16;

    const __half* kp = g_k + ((size_t)bh * TT + c * 64) * DH;
    const __half* vp = g_v + ((size_t)bh * TT + c * 64) * DH;
    const int lr = tid >> 1, lc = (tid & 1) * 32;
    #pragma unroll
    for (int u = 0; u < 4; u++) {
        *(uint4*)(Ks + lr * SR + lc + u * 8) = *(const uint4*)(kp + lr * 64 + lc + u * 8);
        *(uint4*)(Vs + lr * SR + lc + u * 8) = *(const uint4*)(vp + lr * 64 + lc + u * 8);
    }
    __syncthreads();

    const uint32_t kb = smem_u32(Ks), vb = smem_u32(Vs);
    float acc[8][4];
    #pragma unroll
    for (int i = 0; i < 8; i++)
        #pragma unroll
        for (int q = 0; q < 4; q++) acc[i][q] = 0.f;

    #pragma unroll
    for (int ks = 0; ks < 4; ks++) {
        const int t0 = ks * 16;
        uint32_t ka[4];
        ldsm4t(ka, kb + (uint32_t)(t0 + ((lane >> 4) & 1) * 8 + (lane & 7)) * (SR * 2)
                     + wm * 2 + ((lane >> 3) & 1) * 16);
        #pragma unroll
        for (int ntp = 0; ntp < 4; ntp++) {
            uint32_t t[4];
            ldsm4t(t, vb + (uint32_t)(t0 + ((lane >> 3) & 1) * 8 + (lane & 7)) * (SR * 2)
                        + ntp * 32 + ((lane >> 4) & 1) * 16);
            uint32_t b0[2] = { t[0], t[1] }, b1[2] = { t[2], t[3] };
            mma16816(acc[2 * ntp],     ka, b0);
            mma16816(acc[2 * ntp + 1], ka, b1);
        }
    }

    __half* kvout = g_kvh + ((size_t)bh * NC + c) * 4096;
    #pragma unroll
    for (int nt = 0; nt < 8; nt++) {
        const int col = nt * 8 + 2 * tig;
        *(uint32_t*)(kvout + (wm + g) * 64 + col)     = packf2h(acc[nt][0], acc[nt][1]);
        *(uint32_t*)(kvout + (wm + g + 8) * 64 + col) = packf2h(acc[nt][2], acc[nt][3]);
    }

    if (tid < 64) {
        float s = 0.f;
        #pragma unroll 8
        for (int t = 0; t < 64; t++) s += __half2float(Ks[t * SR + tid]);
        g_ks[((size_t)bh * NC + c) * 64 + tid] = s;
    }
}

// ---------------------------------------------------------------------------
// Exclusive prefix scan across chunks; fp16 in (g_kvh), fp16 out (g_sh).
// 2 adjacent positions per thread (__half2); register-prefetched (MLP=32).
// grid (8, BH) x 256 threads.
// ---------------------------------------------------------------------------
__global__ __launch_bounds__(256) void prefix_scan()
{
    const int bh = blockIdx.y;
    const int p2 = blockIdx.x * 256 + threadIdx.x;   // 0..2047 (pairs)
    const __half* base = g_kvh + (size_t)bh * NC * 4096 + p2 * 2;
    __half* outp = g_sh + (size_t)bh * NC * 4096 + p2 * 2;

    __half2 v[NC];
    #pragma unroll
    for (int c = 0; c < NC; c++) v[c] = *(const __half2*)(base + c * 4096);
    float2 run = make_float2(0.f, 0.f);
    #pragma unroll
    for (int c = 0; c < NC; c++) {
        *(__half2*)(outp + c * 4096) = __floats2half2_rn(run.x, run.y);
        float2 f = __half22float2(v[c]);
        run.x += f.x; run.y += f.y;
    }

    if (blockIdx.x == 0 && threadIdx.x < 64) {
        float w[NC];
        float* kbp = g_ks + (size_t)bh * NC * 64 + threadIdx.x;
        #pragma unroll
        for (int c = 0; c < NC; c++) w[c] = kbp[c * 64];
        float r2 = 0.f;
        #pragma unroll
        for (int c = 0; c < NC; c++) {
            kbp[c * 64] = r2;
            r2 += w[c];
        }
    }
}

// ---------------------------------------------------------------------------
// Attention chunk via mma: A = mask(QK^T); out = (A V + Q S) / (rowsum(A)+Qz)
// Q/K load synchronously; V/S prefetch via cp.async overlapped with GEMM1.
// Writes fp16 g_ah for the O-gemm.
// ---------------------------------------------------------------------------
__global__ __launch_bounds__(128) void attn_mma()
{
    __shared__ __half Qs[64 * SR];
    __shared__ __half Ks[64 * SR];   // K, then reused as A
    __shared__ __half Vs[64 * SR];
    __shared__ __half Ss[64 * SR];
    __shared__ float  zs[64];

    const int c = blockIdx.x, bh = blockIdx.y;
    const int tid = threadIdx.x;
    const int wid = tid >> 5, lane = tid & 31;
    const int g = lane >> 2, tig = lane & 3;
    const int wm = wid * 16;

    const __half* qp = g_q + ((size_t)bh * TT + c * 64) * DH;
    const __half* kp = g_k + ((size_t)bh * TT + c * 64) * DH;
    const __half* vp = g_v + ((size_t)bh * TT + c * 64) * DH;
    const __half* sp = g_sh + ((size_t)bh * NC + c) * 4096;

    const int lr = tid >> 1, lc = (tid & 1) * 32;
    const uint32_t vsm = smem_u32(Vs), ssm = smem_u32(Ss);
    // async prefetch of V and S (first used after the A-write barrier)
    #pragma unroll
    for (int u = 0; u < 2; u++) {
        const uint32_t so = (uint32_t)lr * (SR * 2) + (lc + u * 16) * 2;
        cp16(vsm + so,      vp + lr * 64 + lc + u * 16);
        cp16(vsm + so + 16, vp + lr * 64 + lc + u * 16 + 8);
        cp16(ssm + so,      sp + lr * 64 + lc + u * 16);
        cp16(ssm + so + 16, sp + lr * 64 + lc + u * 16 + 8);
    }
    CP_COMMIT();
    // synchronous Q/K loads (needed for GEMM1 immediately)
    #pragma unroll
    for (int u = 0; u < 4; u++) {
        *(uint4*)(Qs + lr * SR + lc + u * 8) = *(const uint4*)(qp + lr * 64 + lc + u * 8);
        *(uint4*)(Ks + lr * SR + lc + u * 8) = *(const uint4*)(kp + lr * 64 + lc + u * 8);
    }
    if (tid < 64) zs[tid] = g_ks[((size_t)bh * NC + c) * 64 + tid];
    __syncthreads();

    const uint32_t qb = smem_u32(Qs), kb = smem_u32(Ks);
    const uint32_t vb = vsm, sb = ssm;

    // ---- GEMM1: A = Q K^T ----
    float aa[8][4];
    #pragma unroll
    for (int i = 0; i < 8; i++)
        #pragma unroll
        for (int q = 0; q < 4; q++) aa[i][q] = 0.f;

    #pragma unroll
    for (int ks = 0; ks < 4; ks++) {
        const uint32_t kby = ks * 32;
        uint32_t qa[4];
        ldsm4(qa, qb + (uint32_t)(wm + ((lane >> 3) & 1) * 8 + (lane & 7)) * (SR * 2)
                    + kby + ((lane >> 4) & 1) * 16);
        #pragma unroll
        for (int ntp = 0; ntp < 4; ntp++) {
            uint32_t t[4];
            ldsm4(t, kb + (uint32_t)(ntp * 16 + ((lane >> 4) & 1) * 8 + (lane & 7)) * (SR * 2)
                       + kby + ((lane >> 3) & 1) * 16);
            uint32_t b0[2] = { t[0], t[1] }, b1[2] = { t[2], t[3] };
            mma16816(aa[2 * ntp],     qa, b0);
            mma16816(aa[2 * ntp + 1], qa, b1);
        }
    }

    // mask + rowsum
    const int r0 = wm + g, r1 = r0 + 8;
    float rs0 = 0.f, rs1 = 0.f;
    #pragma unroll
    for (int nt = 0; nt < 8; nt++) {
        const int c0 = nt * 8 + 2 * tig, c1 = c0 + 1;
        if (c0 > r0) aa[nt][0] = 0.f;
        if (c1 > r0) aa[nt][1] = 0.f;
        if (c0 > r1) aa[nt][2] = 0.f;
        if (c1 > r1) aa[nt][3] = 0.f;
        rs0 += aa[nt][0] + aa[nt][1];
        rs1 += aa[nt][2] + aa[nt][3];
    }
    #pragma unroll
    for (int off = 1; off < 4; off <<= 1) {
        rs0 += __shfl_xor_sync(0xffffffffu, rs0, off);
        rs1 += __shfl_xor_sync(0xffffffffu, rs1, off);
    }

    // qz
    float qz0 = 0.f, qz1 = 0.f;
    #pragma unroll 8
    for (int d2 = 0; d2 < 32; d2++) {
        float2 z2 = *(const float2*)(zs + 2 * d2);
        float2 q0 = __half22float2(*(const __half2*)(Qs + r0 * SR + 2 * d2));
        float2 q1 = __half22float2(*(const __half2*)(Qs + r1 * SR + 2 * d2));
        qz0 += q0.x * z2.x + q0.y * z2.y;
        qz1 += q1.x * z2.x + q1.y * z2.y;
    }

    // write masked A (fp16) into Ks
    __syncthreads();
    #pragma unroll
    for (int nt = 0; nt < 8; nt++) {
        const int col = nt * 8 + 2 * tig;
        *(uint32_t*)(Ks + r0 * SR + col) = packf2h(aa[nt][0], aa[nt][1]);
        *(uint32_t*)(Ks + r1 * SR + col) = packf2h(aa[nt][2], aa[nt][3]);
    }
    CP_WAIT0();          // V/S prefetch complete (per-thread)
    __syncthreads();     // publish A + V/S to all threads

    // ---- GEMM2: out = A V + GEMM3: out += Q S ----
    float oc[8][4];
    #pragma unroll
    for (int i = 0; i < 8; i++)
        #pragma unroll
        for (int q = 0; q < 4; q++) oc[i][q] = 0.f;

    #pragma unroll
    for (int ks = 0; ks < 4; ks++) {
        const uint32_t kby = ks * 32;
        uint32_t af[4];
        ldsm4(af, kb + (uint32_t)(wm + ((lane >> 3) & 1) * 8 + (lane & 7)) * (SR * 2)
                    + kby + ((lane >> 4) & 1) * 16);
        #pragma unroll
        for (int ntp = 0; ntp < 4; ntp++) {
            uint32_t t[4];
            ldsm4t(t, vb + (uint32_t)(ks * 16 + ((lane >> 3) & 1) * 8 + (lane & 7)) * (SR * 2)
                        + ntp * 32 + ((lane >> 4) & 1) * 16);
            uint32_t b0[2] = { t[0], t[1] }, b1[2] = { t[2], t[3] };
            mma16816(oc[2 * ntp],     af, b0);
            mma16816(oc[2 * ntp + 1], af, b1);
        }
    }
    #pragma unroll
    for (int ks = 0; ks < 4; ks++) {
        const uint32_t kby = ks * 32;
        uint32_t qa[4];
        ldsm4(qa, qb + (uint32_t)(wm + ((lane >> 3) & 1) * 8 + (lane & 7)) * (SR * 2)
                    + kby + ((lane >> 4) & 1) * 16);
        #pragma unroll
        for (int ntp = 0; ntp < 4; ntp++) {
            uint32_t t[4];
            ldsm4t(t, sb + (uint32_t)(ks * 16 + ((lane >> 3) & 1) * 8 + (lane & 7)) * (SR * 2)
                        + ntp * 32 + ((lane >> 4) & 1) * 16);
            uint32_t b0[2] = { t[0], t[1] }, b1[2] = { t[2], t[3] };
            mma16816(oc[2 * ntp],     qa, b0);
            mma16816(oc[2 * ntp + 1], qa, b1);
        }
    }

    const float inv0 = 1.f / fmaxf(rs0 + qz0, EPSF);
    const float inv1 = 1.f / fmaxf(rs1 + qz1, EPSF);
    const int b = bh >> 4, h = bh & 15;
    __half* p0 = g_ah + ((size_t)(b * TT + c * 64 + r0)) * DD + h * 64;
    __half* p1 = g_ah + ((size_t)(b * TT + c * 64 + r1)) * DD + h * 64;
    #pragma unroll
    for (int nt = 0; nt < 8; nt++) {
        const int col = nt * 8 + 2 * tig;
        *(uint32_t*)(p0 + col) = packf2h(oc[nt][0] * inv0, oc[nt][1] * inv0);
        *(uint32_t*)(p1 + col) = packf2h(oc[nt][2] * inv1, oc[nt][3] * inv1);
    }
}

// ---------------------------------------------------------------------------
extern "C" void kernel_launch(void* const* d_in, const int* in_sizes, int n_in,
                              void* d_out, int out_size)
{
    const float* x  = (const float*)d_in[0];
    const float* Wq = (const float*)d_in[1];
    const float* bq = (const float*)d_in[2];
    const float* Wk = (const float*)d_in[3];
    const float* bk = (const float*)d_in[4];
    const float* Wv = (const float*)d_in[5];
    const float* bv = (const float*)d_in[6];
    const float* Wo = (const float*)d_in[7];
    const float* bo = (const float*)d_in[8];
    float* out = (float*)d_out;

    __half *q, *k, *v, *xh, *wh, *ah;
    cudaGetSymbolAddress((void**)&q,  g_q);
    cudaGetSymbolAddress((void**)&k,  g_k);
    cudaGetSymbolAddress((void**)&v,  g_v);
    cudaGetSymbolAddress((void**)&xh, g_xh);
    cudaGetSymbolAddress((void**)&wh, g_wh);
    cudaGetSymbolAddress((void**)&ah, g_ah);

    cudaFuncSetAttribute(mma_gemm4, cudaFuncAttributeMaxDynamicSharedMemorySize, SMEM_DYN);

    // Fused one-time conversion, fixed 4 float4/thread
    conv_all<<<CN4 / 1024, 256>>>(x, Wq, Wk, Wv, Wo);

    // Fused Q/K/V projections (fp16 out, head layout); Q,K get the feature map.
    mma_gemm4<<<dim3(DD / BN, MM / BM, 3), 256, SMEM_DYN>>>(
        xh, wh, bq, bk, bv, nullptr, q, k, v, 1, 1, 0, /*head_layout=*/1);

    chunk_kv_mma<<<dim3(NC, BH), 128>>>();
    prefix_scan<<<dim3(8, BH), 256>>>();
    attn_mma<<<dim3(NC, BH), 128>>>();

    // Output projection (fp32 out)
    mma_gemm4<<<dim3(DD / BN, MM / BM, 1), 256, SMEM_DYN>>>(
        ah, wh + 3 * (size_t)DD * DD, bo, bo, bo, out, nullptr, nullptr, nullptr,
        0, 0, 0, /*head_layout=*/0);
}